// round 4
// baseline (speedup 1.0000x reference)
#include <cuda_runtime.h>
#include <cstddef>

#define DDIM 512
#define ROWS 3072

__device__ float g_q [ROWS * DDIM];
__device__ float g_ao[ROWS * DDIM];
__device__ float g_S [ROWS * 8 * 128];   // [gq][h][slot]; 0..95 = i/fixed, 96..127 = j-dep

typedef unsigned long long ull;

__device__ __forceinline__ ull dup2(float x) {
    ull r; asm("mov.b64 %0, {%1, %1};" : "=l"(r) : "f"(x)); return r;
}
__device__ __forceinline__ void fma2(ull& d, ull a, ull b) {
    asm("fma.rn.f32x2 %0, %1, %2, %3;" : "=l"(d) : "l"(a), "l"(b), "l"(d));
}
__device__ __forceinline__ float2 unpk(ull v) {
    float2 f; asm("mov.b64 {%0, %1}, %2;" : "=f"(f.x), "=f"(f.y) : "l"(v)); return f;
}

// ---------------------------------------------------------------------------
// GEMM: C[M,N] = A[M,K] @ B[N,K]^T (+bias). BM=BN=64, BK=16, 128 threads.
// Thread tile 8m x 4n via f32x2 (packed along m); B duplicated in smem.
// ---------------------------------------------------------------------------
#define BM 64
#define BN 64
#define BK 16

__global__ __launch_bounds__(128) void gemm_nt(
    const float* __restrict__ A, const float* __restrict__ B,
    const float* __restrict__ bias, float* __restrict__ C,
    int M, int N, int K)
{
    __shared__ float As [BK][BM + 4];
    __shared__ float Bsd[BK][2 * BN + 2];
    const int bm = blockIdx.y * BM;
    const int bn = blockIdx.x * BN;
    const int tid = threadIdx.x;
    const int tx = tid & 15;
    const int ty = tid >> 4;

    ull acc[4][4];
    #pragma unroll
    for (int u = 0; u < 4; u++)
        #pragma unroll
        for (int v = 0; v < 4; v++) acc[u][v] = 0ull;

    for (int k0 = 0; k0 < K; k0 += BK) {
        #pragma unroll
        for (int it = 0; it < 2; it++) {
            int c = tid + 128 * it;
            int m = c >> 2, kg = (c & 3) * 4;
            float4 va = *(const float4*)(A + (size_t)(bm + m) * K + k0 + kg);
            As[kg+0][m] = va.x; As[kg+1][m] = va.y;
            As[kg+2][m] = va.z; As[kg+3][m] = va.w;
            float4 vb = *(const float4*)(B + (size_t)(bn + m) * K + k0 + kg);
            Bsd[kg+0][2*m] = vb.x; Bsd[kg+0][2*m+1] = vb.x;
            Bsd[kg+1][2*m] = vb.y; Bsd[kg+1][2*m+1] = vb.y;
            Bsd[kg+2][2*m] = vb.z; Bsd[kg+2][2*m+1] = vb.z;
            Bsd[kg+3][2*m] = vb.w; Bsd[kg+3][2*m+1] = vb.w;
        }
        __syncthreads();
        #pragma unroll
        for (int kk = 0; kk < BK; kk++) {
            ulonglong2 a0 = *(const ulonglong2*)&As[kk][ty * 8];
            ulonglong2 a1 = *(const ulonglong2*)&As[kk][ty * 8 + 4];
            #pragma unroll
            for (int v = 0; v < 4; v++) {
                ull bd = *(const ull*)&Bsd[kk][2 * (tx * 4 + v)];
                fma2(acc[0][v], a0.x, bd);
                fma2(acc[1][v], a0.y, bd);
                fma2(acc[2][v], a1.x, bd);
                fma2(acc[3][v], a1.y, bd);
            }
        }
        __syncthreads();
    }

    float bv[4] = {0.f, 0.f, 0.f, 0.f};
    if (bias) {
        float4 bb = *(const float4*)(bias + bn + tx * 4);
        bv[0] = bb.x; bv[1] = bb.y; bv[2] = bb.z; bv[3] = bb.w;
    }
    #pragma unroll
    for (int up = 0; up < 4; up++) {
        float o0[4], o1[4];
        #pragma unroll
        for (int v = 0; v < 4; v++) {
            float2 t = unpk(acc[up][v]);
            o0[v] = t.x + bv[v];
            o1[v] = t.y + bv[v];
        }
        float* c0 = C + (size_t)(bm + ty * 8 + 2 * up)     * N + bn + tx * 4;
        float* c1 = C + (size_t)(bm + ty * 8 + 2 * up + 1) * N + bn + tx * 4;
        *(float4*)c0 = make_float4(o0[0], o0[1], o0[2], o0[3]);
        *(float4*)c1 = make_float4(o1[0], o1[1], o1[2], o1[3]);
    }
}

// ---------------------------------------------------------------------------
// Key index mapping (verified rounds 1-2).
// ---------------------------------------------------------------------------
__device__ __forceinline__ int key_gpos(int p, int f, int i, int j)
{
    const int g = f >> 5;
    const int r = f & 31;
    int pos, sp;
    if (p == 0) {
        sp = (f < 64) ? 1 : 2;
        pos = (g == 0) ? r * 32 + i
            : (g == 1) ? 480 + r
            : (g == 2) ? r * 32 + 15
            :            j * 32 + r;
    } else if (p == 1) {
        sp = (f < 64) ? 0 : 2;
        pos = (g == 0) ? r * 32 + i
            : (g == 1) ? 480 + r
            : (g == 2) ? r * 32 + (31 - j)
            :            480 + r;
    } else {
        sp = (f < 64) ? 0 : 2;
        pos = (g == 0) ? r * 32 + 15
            : (g == 1) ? j * 32 + r
            : (g == 2) ? r * 32 + 15
            :            (31 - i) * 32 + r;
    }
    return sp * 1024 + pos;
}

// slot s in [0,96) -> f index, skipping the j-dependent group (3-p)
__device__ __forceinline__ int k1_f(int p, int s)
{
    int g = s >> 5;
    if (g >= 3 - p) g++;
    return g * 32 + (s & 31);
}

// ---------------------------------------------------------------------------
// K1: scores for the 96 i-dep/fixed keys. CTA = (i, h, p); 192 threads.
// Thread tile 4q x 4f (f32x2 along f). Writes g_S slots 0..95 (slot order).
// ---------------------------------------------------------------------------
__global__ __launch_bounds__(192) void k1_scores()
{
    const int i = blockIdx.x, h = blockIdx.y, p = blockIdx.z;
    const int tid = threadIdx.x;

    __shared__ int   spos[96];
    __shared__ float Ks[64][96];   // [d][slot]
    __shared__ float Qs[64][32];   // [d][q]

    if (tid < 96) spos[tid] = key_gpos(p, k1_f(p, tid), i, 0);
    __syncthreads();

    #pragma unroll
    for (int it = 0; it < 8; it++) {
        int idx = tid + 192 * it;          // 0..1535
        int kk = idx % 96, dg = (idx / 96) * 4;
        float4 v = *(const float4*)(g_q + (size_t)spos[kk] * DDIM + h * 64 + dg);
        Ks[dg+0][kk] = v.x; Ks[dg+1][kk] = v.y;
        Ks[dg+2][kk] = v.z; Ks[dg+3][kk] = v.w;
    }
    #pragma unroll
    for (int it = 0; it < 3; it++) {
        int idx = tid + 192 * it;
        if (idx < 512) {
            int q = idx & 31, dg = (idx >> 5) * 4;
            float4 v = *(const float4*)(g_q + (size_t)(p*1024 + q*32 + i) * DDIM + h*64 + dg);
            Qs[dg+0][q] = v.x; Qs[dg+1][q] = v.y;
            Qs[dg+2][q] = v.z; Qs[dg+3][q] = v.w;
        }
    }
    __syncthreads();

    const int qy = tid / 24, fx = tid % 24;
    ull acc[4][2];
    #pragma unroll
    for (int u = 0; u < 4; u++) { acc[u][0] = 0ull; acc[u][1] = 0ull; }

    #pragma unroll 4
    for (int d = 0; d < 64; d++) {
        float4 q4 = *(const float4*)&Qs[d][qy * 4];
        ulonglong2 kv = *(const ulonglong2*)&Ks[d][fx * 4];
        ull qd;
        qd = dup2(q4.x); fma2(acc[0][0], qd, kv.x); fma2(acc[0][1], qd, kv.y);
        qd = dup2(q4.y); fma2(acc[1][0], qd, kv.x); fma2(acc[1][1], qd, kv.y);
        qd = dup2(q4.z); fma2(acc[2][0], qd, kv.x); fma2(acc[2][1], qd, kv.y);
        qd = dup2(q4.w); fma2(acc[3][0], qd, kv.x); fma2(acc[3][1], qd, kv.y);
    }

    #pragma unroll
    for (int u = 0; u < 4; u++) {
        int q = qy * 4 + u;
        size_t base = ((size_t)(p*1024 + q*32 + i) * 8 + h) * 128 + fx * 4;
        float2 e0 = unpk(acc[u][0]);
        float2 e1 = unpk(acc[u][1]);
        *(float4*)(g_S + base) = make_float4(e0.x*0.125f, e0.y*0.125f,
                                             e1.x*0.125f, e1.y*0.125f);
    }
}

// ---------------------------------------------------------------------------
// K2: j-dep scores (slots 96..127) + softmax over 128 + j-part of output.
// CTA = (j, h, p); 256 threads.
// ---------------------------------------------------------------------------
__global__ __launch_bounds__(256) void k2_mid()
{
    const int j = blockIdx.x, h = blockIdx.y, p = blockIdx.z;
    const int tid = threadIdx.x;
    const int qbase = p * 1024 + j * 32;

    __shared__ int   spos[32];
    __shared__ float Kd[64][32];    // [d][f]
    __shared__ float Kf[32][68];    // [f][d]
    __shared__ float Qs[64][32];    // [d][q]
    __shared__ float Sall[32][132]; // [q][slot]

    if (tid < 32) spos[tid] = key_gpos(p, (3 - p) * 32 + tid, 0, j);
    __syncthreads();

    #pragma unroll
    for (int it = 0; it < 2; it++) {
        int idx = tid + 256 * it;          // 0..511
        int q = idx & 31, dg = (idx >> 5) * 4;
        float4 v = *(const float4*)(g_q + (size_t)(qbase + q) * DDIM + h * 64 + dg);
        Qs[dg+0][q] = v.x; Qs[dg+1][q] = v.y; Qs[dg+2][q] = v.z; Qs[dg+3][q] = v.w;
        float4 w = *(const float4*)(g_q + (size_t)spos[q] * DDIM + h * 64 + dg);
        Kd[dg+0][q] = w.x; Kd[dg+1][q] = w.y; Kd[dg+2][q] = w.z; Kd[dg+3][q] = w.w;
        *(float4*)&Kf[q][dg] = w;
    }
    #pragma unroll
    for (int it = 0; it < 3; it++) {
        int idx = tid + 256 * it;          // 0..767
        int q = idx / 24, sg = (idx % 24) * 4;
        *(float4*)&Sall[q][sg] =
            *(const float4*)(g_S + ((size_t)(qbase + q) * 8 + h) * 128 + sg);
    }
    __syncthreads();

    // scores for the 32 j-dep keys: 2q x 2f per thread
    {
        const int qy2 = tid >> 4, fx2 = tid & 15;
        ull a0 = 0ull, a1 = 0ull;
        #pragma unroll 8
        for (int d = 0; d < 64; d++) {
            float2 q2 = *(const float2*)&Qs[d][qy2 * 2];
            ull kv = *(const ull*)&Kd[d][fx2 * 2];
            fma2(a0, dup2(q2.x), kv);
            fma2(a1, dup2(q2.y), kv);
        }
        float2 s0 = unpk(a0), s1 = unpk(a1);
        Sall[qy2*2  ][96 + fx2*2]     = s0.x * 0.125f;
        Sall[qy2*2  ][96 + fx2*2 + 1] = s0.y * 0.125f;
        Sall[qy2*2+1][96 + fx2*2]     = s1.x * 0.125f;
        Sall[qy2*2+1][96 + fx2*2 + 1] = s1.y * 0.125f;
    }
    __syncthreads();

    // softmax over 128 slots (8 lanes per query, 16 vals each)
    {
        const int qs = tid >> 3, l8 = tid & 7;
        float vals[16];
        float m = -1e30f;
        #pragma unroll
        for (int u = 0; u < 16; u++) {
            vals[u] = Sall[qs][l8 + 8 * u];
            m = fmaxf(m, vals[u]);
        }
        #pragma unroll
        for (int off = 4; off; off >>= 1)
            m = fmaxf(m, __shfl_xor_sync(0xffffffffu, m, off));
        float sum = 0.f;
        #pragma unroll
        for (int u = 0; u < 16; u++) { vals[u] = __expf(vals[u] - m); sum += vals[u]; }
        #pragma unroll
        for (int off = 4; off; off >>= 1)
            sum += __shfl_xor_sync(0xffffffffu, sum, off);
        const float inv = 1.0f / sum;
        #pragma unroll
        for (int u = 0; u < 16; u++)
            Sall[qs][l8 + 8 * u] = vals[u] * inv;
    }
    __syncthreads();

    // write normalized P back to g_S (float4-contiguous)
    #pragma unroll
    for (int it = 0; it < 4; it++) {
        int c = tid + 256 * it;
        int q = c >> 5, f4 = (c & 31) * 4;
        *(float4*)(g_S + ((size_t)(qbase + q) * 8 + h) * 128 + f4) =
            *(const float4*)&Sall[q][f4];
    }

    // O_j = P_j(32x32) @ K_j(32x64): 2q x 4d per thread
    {
        const int qy = tid >> 4, dx = tid & 15;
        ull o00 = 0ull, o01 = 0ull, o10 = 0ull, o11 = 0ull;
        #pragma unroll 8
        for (int r = 0; r < 32; r++) {
            float pa = Sall[qy*2  ][96 + r];
            float pb = Sall[qy*2+1][96 + r];
            ulonglong2 kv = *(const ulonglong2*)&Kf[r][dx * 4];
            ull da = dup2(pa), db = dup2(pb);
            fma2(o00, da, kv.x); fma2(o01, da, kv.y);
            fma2(o10, db, kv.x); fma2(o11, db, kv.y);
        }
        float2 t0 = unpk(o00), t1 = unpk(o01);
        *(float4*)(g_ao + (size_t)(qbase + qy*2) * DDIM + h*64 + dx*4) =
            make_float4(t0.x, t0.y, t1.x, t1.y);
        t0 = unpk(o10); t1 = unpk(o11);
        *(float4*)(g_ao + (size_t)(qbase + qy*2 + 1) * DDIM + h*64 + dx*4) =
            make_float4(t0.x, t0.y, t1.x, t1.y);
    }
}

// ---------------------------------------------------------------------------
// K3: i-part of output. CTA = (i, h, p); 128 threads, 4q x 4d per thread,
// s-loop unrolled by 4 with float4 prob loads. O += P96(32x96) @ K96(96x64).
// ---------------------------------------------------------------------------
__global__ __launch_bounds__(128) void k3_out()
{
    const int i = blockIdx.x, h = blockIdx.y, p = blockIdx.z;
    const int tid = threadIdx.x;

    __shared__ int   spos[96];
    __shared__ float Ks[96][64];    // [slot][d]
    __shared__ float Ps[32][100];   // [q][slot]

    if (tid < 96) spos[tid] = key_gpos(p, k1_f(p, tid), i, 0);
    __syncthreads();

    #pragma unroll
    for (int it = 0; it < 12; it++) {
        int c = tid + 128 * it;            // 0..1535
        int key = c >> 4, dg = (c & 15) * 4;
        *(float4*)&Ks[key][dg] =
            *(const float4*)(g_q + (size_t)spos[key] * DDIM + h * 64 + dg);
    }
    #pragma unroll
    for (int it = 0; it < 6; it++) {
        int idx = tid + 128 * it;          // 0..767
        int q = idx / 24, sg = (idx % 24) * 4;
        *(float4*)&Ps[q][sg] =
            *(const float4*)(g_S + ((size_t)(p*1024 + q*32 + i) * 8 + h) * 128 + sg);
    }
    __syncthreads();

    const int qy = tid >> 4, dx = tid & 15;
    ull o[4][2];
    #pragma unroll
    for (int u = 0; u < 4; u++) { o[u][0] = 0ull; o[u][1] = 0ull; }

    for (int s0 = 0; s0 < 96; s0 += 4) {
        float pa[4][4];
        #pragma unroll
        for (int u = 0; u < 4; u++)
            *(float4*)&pa[u][0] = *(const float4*)&Ps[qy * 4 + u][s0];
        #pragma unroll
        for (int t = 0; t < 4; t++) {
            ulonglong2 kv = *(const ulonglong2*)&Ks[s0 + t][dx * 4];
            #pragma unroll
            for (int u = 0; u < 4; u++) {
                ull pd = dup2(pa[u][t]);
                fma2(o[u][0], pd, kv.x);
                fma2(o[u][1], pd, kv.y);
            }
        }
    }

    #pragma unroll
    for (int u = 0; u < 4; u++) {
        size_t off = (size_t)(p*1024 + (qy*4 + u)*32 + i) * DDIM + h*64 + dx*4;
        float4 old = *(const float4*)(g_ao + off);
        float2 t0 = unpk(o[u][0]), t1 = unpk(o[u][1]);
        *(float4*)(g_ao + off) = make_float4(old.x + t0.x, old.y + t0.y,
                                             old.z + t1.x, old.w + t1.y);
    }
}

// ---------------------------------------------------------------------------
extern "C" void kernel_launch(void* const* d_in, const int* in_sizes, int n_in,
                              void* d_out, int out_size)
{
    const float* x  = (const float*)d_in[0];
    const float* Wq = (const float*)d_in[1];
    const float* Wo = (const float*)d_in[2];
    const float* bo = (const float*)d_in[3];
    float* out = (float*)d_out;

    float *qp = nullptr, *aop = nullptr;
    cudaGetSymbolAddress((void**)&qp,  g_q);
    cudaGetSymbolAddress((void**)&aop, g_ao);

    const dim3 gridG(512 / BN, ROWS / BM);   // (8, 48)
    const dim3 gridA(32, 8, 3);              // (i|j, head, plane)

    gemm_nt<<<gridG, 128>>>(x, Wq, nullptr, qp, ROWS, 512, 512);
    k1_scores<<<gridA, 192>>>();
    k2_mid  <<<gridA, 256>>>();
    k3_out  <<<gridA, 128>>>();
    gemm_nt<<<gridG, 128>>>(aop, Wo, bo, out, ROWS, 512, 512);
}

// round 5
// speedup vs baseline: 1.2463x; 1.2463x over previous
#include <cuda_runtime.h>
#include <cstddef>

#define DDIM 512
#define ROWS 3072

__device__ float g_q [ROWS * DDIM];
__device__ float g_ao[ROWS * DDIM];
__device__ float g_S [ROWS * 8 * 128];   // [gq][h][slot]; 0..95 = i/fixed, 96..127 = j-dep

typedef unsigned long long ull;

__device__ __forceinline__ ull dup2(float x) {
    ull r; asm("mov.b64 %0, {%1, %1};" : "=l"(r) : "f"(x)); return r;
}
__device__ __forceinline__ void fma2(ull& d, ull a, ull b) {
    asm("fma.rn.f32x2 %0, %1, %2, %3;" : "=l"(d) : "l"(a), "l"(b), "l"(d));
}
__device__ __forceinline__ float2 unpk(ull v) {
    float2 f; asm("mov.b64 {%0, %1}, %2;" : "=f"(f.x), "=f"(f.y) : "l"(v)); return f;
}
__device__ __forceinline__ float tf32r(float x) {
    unsigned u; asm("cvt.rna.tf32.f32 %0, %1;" : "=r"(u) : "f"(x));
    return __uint_as_float(u);
}
__device__ __forceinline__ void mma_tf32(float* c, const unsigned* a, const unsigned* b) {
    asm volatile(
        "mma.sync.aligned.m16n8k8.row.col.f32.tf32.tf32.f32 "
        "{%0,%1,%2,%3}, {%4,%5,%6,%7}, {%8,%9}, {%0,%1,%2,%3};"
        : "+f"(c[0]), "+f"(c[1]), "+f"(c[2]), "+f"(c[3])
        : "r"(a[0]), "r"(a[1]), "r"(a[2]), "r"(a[3]), "r"(b[0]), "r"(b[1]));
}

// ---------------------------------------------------------------------------
// GEMM: C[M,N] = A[M,K] @ B[N,K]^T (+bias), tf32x2 split (fp32-grade accuracy).
// BM=128, BN=64, BK=16; 256 threads = 8 warps (4 m x 2 n), warp tile 32x32.
// Per warp: 2 m16-tiles x 4 n8-tiles; 3 MMAs per tile (hi*hi, hi*lo, lo*hi).
// smem [k][m]/[k][n] with pad 8 -> conflict-free fragment loads.
// ---------------------------------------------------------------------------
#define BM 128
#define BN 64
#define BK 16

__global__ __launch_bounds__(256) void gemm_tf32(
    const float* __restrict__ A, const float* __restrict__ B,
    const float* __restrict__ bias, float* __restrict__ C,
    int M, int N, int K)
{
    __shared__ float As_hi[BK][BM + 8];
    __shared__ float As_lo[BK][BM + 8];
    __shared__ float Bs_hi[BK][BN + 8];
    __shared__ float Bs_lo[BK][BN + 8];

    const int bm = blockIdx.y * BM;
    const int bn = blockIdx.x * BN;
    const int tid  = threadIdx.x;
    const int warp = tid >> 5;
    const int lane = tid & 31;
    const int wm = warp & 3;        // 0..3  (m)
    const int wn = warp >> 2;       // 0..1  (n)
    const int r4 = lane >> 2;       // 0..7
    const int kq = lane & 3;        // 0..3

    float acc[2][4][4];
    #pragma unroll
    for (int mt = 0; mt < 2; mt++)
        #pragma unroll
        for (int nt = 0; nt < 4; nt++)
            #pragma unroll
            for (int u = 0; u < 4; u++) acc[mt][nt][u] = 0.f;

    #pragma unroll 1
    for (int k0 = 0; k0 < K; k0 += BK) {
        // stage A (128x16) split hi/lo
        #pragma unroll
        for (int it = 0; it < 2; it++) {
            int c = tid + 256 * it;            // 0..511
            int m = c >> 2, kg = (c & 3) * 4;
            float4 v = *(const float4*)(A + (size_t)(bm + m) * K + k0 + kg);
            float h;
            h = tf32r(v.x); As_hi[kg+0][m] = h; As_lo[kg+0][m] = tf32r(v.x - h);
            h = tf32r(v.y); As_hi[kg+1][m] = h; As_lo[kg+1][m] = tf32r(v.y - h);
            h = tf32r(v.z); As_hi[kg+2][m] = h; As_lo[kg+2][m] = tf32r(v.z - h);
            h = tf32r(v.w); As_hi[kg+3][m] = h; As_lo[kg+3][m] = tf32r(v.w - h);
        }
        // stage B (64x16) split hi/lo
        {
            int m = tid >> 2, kg = (tid & 3) * 4;
            float4 v = *(const float4*)(B + (size_t)(bn + m) * K + k0 + kg);
            float h;
            h = tf32r(v.x); Bs_hi[kg+0][m] = h; Bs_lo[kg+0][m] = tf32r(v.x - h);
            h = tf32r(v.y); Bs_hi[kg+1][m] = h; Bs_lo[kg+1][m] = tf32r(v.y - h);
            h = tf32r(v.z); Bs_hi[kg+2][m] = h; Bs_lo[kg+2][m] = tf32r(v.z - h);
            h = tf32r(v.w); Bs_hi[kg+3][m] = h; Bs_lo[kg+3][m] = tf32r(v.w - h);
        }
        __syncthreads();

        #pragma unroll
        for (int ks = 0; ks < BK; ks += 8) {
            unsigned bh[4][2], bl[4][2];
            #pragma unroll
            for (int nt = 0; nt < 4; nt++) {
                int col = wn * 32 + nt * 8 + r4;
                bh[nt][0] = __float_as_uint(Bs_hi[ks + kq    ][col]);
                bh[nt][1] = __float_as_uint(Bs_hi[ks + kq + 4][col]);
                bl[nt][0] = __float_as_uint(Bs_lo[ks + kq    ][col]);
                bl[nt][1] = __float_as_uint(Bs_lo[ks + kq + 4][col]);
            }
            #pragma unroll
            for (int mt = 0; mt < 2; mt++) {
                int row = wm * 32 + mt * 16 + r4;
                unsigned ah[4], al[4];
                ah[0] = __float_as_uint(As_hi[ks + kq    ][row]);
                ah[1] = __float_as_uint(As_hi[ks + kq    ][row + 8]);
                ah[2] = __float_as_uint(As_hi[ks + kq + 4][row]);
                ah[3] = __float_as_uint(As_hi[ks + kq + 4][row + 8]);
                al[0] = __float_as_uint(As_lo[ks + kq    ][row]);
                al[1] = __float_as_uint(As_lo[ks + kq    ][row + 8]);
                al[2] = __float_as_uint(As_lo[ks + kq + 4][row]);
                al[3] = __float_as_uint(As_lo[ks + kq + 4][row + 8]);
                #pragma unroll
                for (int nt = 0; nt < 4; nt++) {
                    mma_tf32(acc[mt][nt], ah, bl[nt]);   // hi*lo
                    mma_tf32(acc[mt][nt], al, bh[nt]);   // lo*hi
                    mma_tf32(acc[mt][nt], ah, bh[nt]);   // hi*hi
                }
            }
        }
        __syncthreads();
    }

    // epilogue
    #pragma unroll
    for (int nt = 0; nt < 4; nt++) {
        int col = bn + wn * 32 + nt * 8 + 2 * kq;
        float2 bb = make_float2(0.f, 0.f);
        if (bias) bb = *(const float2*)(bias + col);
        #pragma unroll
        for (int mt = 0; mt < 2; mt++) {
            int row0 = bm + wm * 32 + mt * 16 + r4;
            *(float2*)(C + (size_t)row0 * N + col) =
                make_float2(acc[mt][nt][0] + bb.x, acc[mt][nt][1] + bb.y);
            *(float2*)(C + (size_t)(row0 + 8) * N + col) =
                make_float2(acc[mt][nt][2] + bb.x, acc[mt][nt][3] + bb.y);
        }
    }
}

// ---------------------------------------------------------------------------
// Key index mapping (verified rounds 1-4).
// ---------------------------------------------------------------------------
__device__ __forceinline__ int key_gpos(int p, int f, int i, int j)
{
    const int g = f >> 5;
    const int r = f & 31;
    int pos, sp;
    if (p == 0) {
        sp = (f < 64) ? 1 : 2;
        pos = (g == 0) ? r * 32 + i
            : (g == 1) ? 480 + r
            : (g == 2) ? r * 32 + 15
            :            j * 32 + r;
    } else if (p == 1) {
        sp = (f < 64) ? 0 : 2;
        pos = (g == 0) ? r * 32 + i
            : (g == 1) ? 480 + r
            : (g == 2) ? r * 32 + (31 - j)
            :            480 + r;
    } else {
        sp = (f < 64) ? 0 : 2;
        pos = (g == 0) ? r * 32 + 15
            : (g == 1) ? j * 32 + r
            : (g == 2) ? r * 32 + 15
            :            (31 - i) * 32 + r;
    }
    return sp * 1024 + pos;
}

__device__ __forceinline__ int k1_f(int p, int s)
{
    int g = s >> 5;
    if (g >= 3 - p) g++;
    return g * 32 + (s & 31);
}

// ---------------------------------------------------------------------------
// K1: scores for the 96 i-dep/fixed keys. CTA = (i, h, p); 192 threads.
// ---------------------------------------------------------------------------
__global__ __launch_bounds__(192) void k1_scores()
{
    const int i = blockIdx.x, h = blockIdx.y, p = blockIdx.z;
    const int tid = threadIdx.x;

    __shared__ int   spos[96];
    __shared__ float Ks[64][96];
    __shared__ float Qs[64][32];

    if (tid < 96) spos[tid] = key_gpos(p, k1_f(p, tid), i, 0);
    __syncthreads();

    #pragma unroll
    for (int it = 0; it < 8; it++) {
        int idx = tid + 192 * it;
        int kk = idx % 96, dg = (idx / 96) * 4;
        float4 v = *(const float4*)(g_q + (size_t)spos[kk] * DDIM + h * 64 + dg);
        Ks[dg+0][kk] = v.x; Ks[dg+1][kk] = v.y;
        Ks[dg+2][kk] = v.z; Ks[dg+3][kk] = v.w;
    }
    #pragma unroll
    for (int it = 0; it < 3; it++) {
        int idx = tid + 192 * it;
        if (idx < 512) {
            int q = idx & 31, dg = (idx >> 5) * 4;
            float4 v = *(const float4*)(g_q + (size_t)(p*1024 + q*32 + i) * DDIM + h*64 + dg);
            Qs[dg+0][q] = v.x; Qs[dg+1][q] = v.y;
            Qs[dg+2][q] = v.z; Qs[dg+3][q] = v.w;
        }
    }
    __syncthreads();

    const int qy = tid / 24, fx = tid % 24;
    ull acc[4][2];
    #pragma unroll
    for (int u = 0; u < 4; u++) { acc[u][0] = 0ull; acc[u][1] = 0ull; }

    #pragma unroll 4
    for (int d = 0; d < 64; d++) {
        float4 q4 = *(const float4*)&Qs[d][qy * 4];
        ulonglong2 kv = *(const ulonglong2*)&Ks[d][fx * 4];
        ull qd;
        qd = dup2(q4.x); fma2(acc[0][0], qd, kv.x); fma2(acc[0][1], qd, kv.y);
        qd = dup2(q4.y); fma2(acc[1][0], qd, kv.x); fma2(acc[1][1], qd, kv.y);
        qd = dup2(q4.z); fma2(acc[2][0], qd, kv.x); fma2(acc[2][1], qd, kv.y);
        qd = dup2(q4.w); fma2(acc[3][0], qd, kv.x); fma2(acc[3][1], qd, kv.y);
    }

    #pragma unroll
    for (int u = 0; u < 4; u++) {
        int q = qy * 4 + u;
        size_t base = ((size_t)(p*1024 + q*32 + i) * 8 + h) * 128 + fx * 4;
        float2 e0 = unpk(acc[u][0]);
        float2 e1 = unpk(acc[u][1]);
        *(float4*)(g_S + base) = make_float4(e0.x*0.125f, e0.y*0.125f,
                                             e1.x*0.125f, e1.y*0.125f);
    }
}

// ---------------------------------------------------------------------------
// K2: j-dep scores (slots 96..127) + softmax + j-part of output.
// ---------------------------------------------------------------------------
__global__ __launch_bounds__(256) void k2_mid()
{
    const int j = blockIdx.x, h = blockIdx.y, p = blockIdx.z;
    const int tid = threadIdx.x;
    const int qbase = p * 1024 + j * 32;

    __shared__ int   spos[32];
    __shared__ float Kd[64][32];
    __shared__ float Kf[32][68];
    __shared__ float Qs[64][32];
    __shared__ float Sall[32][132];

    if (tid < 32) spos[tid] = key_gpos(p, (3 - p) * 32 + tid, 0, j);
    __syncthreads();

    #pragma unroll
    for (int it = 0; it < 2; it++) {
        int idx = tid + 256 * it;
        int q = idx & 31, dg = (idx >> 5) * 4;
        float4 v = *(const float4*)(g_q + (size_t)(qbase + q) * DDIM + h * 64 + dg);
        Qs[dg+0][q] = v.x; Qs[dg+1][q] = v.y; Qs[dg+2][q] = v.z; Qs[dg+3][q] = v.w;
        float4 w = *(const float4*)(g_q + (size_t)spos[q] * DDIM + h * 64 + dg);
        Kd[dg+0][q] = w.x; Kd[dg+1][q] = w.y; Kd[dg+2][q] = w.z; Kd[dg+3][q] = w.w;
        *(float4*)&Kf[q][dg] = w;
    }
    #pragma unroll
    for (int it = 0; it < 3; it++) {
        int idx = tid + 256 * it;
        int q = idx / 24, sg = (idx % 24) * 4;
        *(float4*)&Sall[q][sg] =
            *(const float4*)(g_S + ((size_t)(qbase + q) * 8 + h) * 128 + sg);
    }
    __syncthreads();

    {
        const int qy2 = tid >> 4, fx2 = tid & 15;
        ull a0 = 0ull, a1 = 0ull;
        #pragma unroll 8
        for (int d = 0; d < 64; d++) {
            float2 q2 = *(const float2*)&Qs[d][qy2 * 2];
            ull kv = *(const ull*)&Kd[d][fx2 * 2];
            fma2(a0, dup2(q2.x), kv);
            fma2(a1, dup2(q2.y), kv);
        }
        float2 s0 = unpk(a0), s1 = unpk(a1);
        Sall[qy2*2  ][96 + fx2*2]     = s0.x * 0.125f;
        Sall[qy2*2  ][96 + fx2*2 + 1] = s0.y * 0.125f;
        Sall[qy2*2+1][96 + fx2*2]     = s1.x * 0.125f;
        Sall[qy2*2+1][96 + fx2*2 + 1] = s1.y * 0.125f;
    }
    __syncthreads();

    {
        const int qs = tid >> 3, l8 = tid & 7;
        float vals[16];
        float m = -1e30f;
        #pragma unroll
        for (int u = 0; u < 16; u++) {
            vals[u] = Sall[qs][l8 + 8 * u];
            m = fmaxf(m, vals[u]);
        }
        #pragma unroll
        for (int off = 4; off; off >>= 1)
            m = fmaxf(m, __shfl_xor_sync(0xffffffffu, m, off));
        float sum = 0.f;
        #pragma unroll
        for (int u = 0; u < 16; u++) { vals[u] = __expf(vals[u] - m); sum += vals[u]; }
        #pragma unroll
        for (int off = 4; off; off >>= 1)
            sum += __shfl_xor_sync(0xffffffffu, sum, off);
        const float inv = 1.0f / sum;
        #pragma unroll
        for (int u = 0; u < 16; u++)
            Sall[qs][l8 + 8 * u] = vals[u] * inv;
    }
    __syncthreads();

    #pragma unroll
    for (int it = 0; it < 4; it++) {
        int c = tid + 256 * it;
        int q = c >> 5, f4 = (c & 31) * 4;
        *(float4*)(g_S + ((size_t)(qbase + q) * 8 + h) * 128 + f4) =
            *(const float4*)&Sall[q][f4];
    }

    {
        const int qy = tid >> 4, dx = tid & 15;
        ull o00 = 0ull, o01 = 0ull, o10 = 0ull, o11 = 0ull;
        #pragma unroll 8
        for (int r = 0; r < 32; r++) {
            float pa = Sall[qy*2  ][96 + r];
            float pb = Sall[qy*2+1][96 + r];
            ulonglong2 kv = *(const ulonglong2*)&Kf[r][dx * 4];
            ull da = dup2(pa), db = dup2(pb);
            fma2(o00, da, kv.x); fma2(o01, da, kv.y);
            fma2(o10, db, kv.x); fma2(o11, db, kv.y);
        }
        float2 t0 = unpk(o00), t1 = unpk(o01);
        *(float4*)(g_ao + (size_t)(qbase + qy*2) * DDIM + h*64 + dx*4) =
            make_float4(t0.x, t0.y, t1.x, t1.y);
        t0 = unpk(o10); t1 = unpk(o11);
        *(float4*)(g_ao + (size_t)(qbase + qy*2 + 1) * DDIM + h*64 + dx*4) =
            make_float4(t0.x, t0.y, t1.x, t1.y);
    }
}

// ---------------------------------------------------------------------------
// K3: i-part of output. CTA = (i, h, p); 128 threads, 4q x 4d tiles.
// ---------------------------------------------------------------------------
__global__ __launch_bounds__(128) void k3_out()
{
    const int i = blockIdx.x, h = blockIdx.y, p = blockIdx.z;
    const int tid = threadIdx.x;

    __shared__ int   spos[96];
    __shared__ float Ks[96][64];
    __shared__ float Ps[32][100];

    if (tid < 96) spos[tid] = key_gpos(p, k1_f(p, tid), i, 0);
    __syncthreads();

    #pragma unroll
    for (int it = 0; it < 12; it++) {
        int c = tid + 128 * it;
        int key = c >> 4, dg = (c & 15) * 4;
        *(float4*)&Ks[key][dg] =
            *(const float4*)(g_q + (size_t)spos[key] * DDIM + h * 64 + dg);
    }
    #pragma unroll
    for (int it = 0; it < 6; it++) {
        int idx = tid + 128 * it;
        int q = idx / 24, sg = (idx % 24) * 4;
        *(float4*)&Ps[q][sg] =
            *(const float4*)(g_S + ((size_t)(p*1024 + q*32 + i) * 8 + h) * 128 + sg);
    }
    __syncthreads();

    const int qy = tid >> 4, dx = tid & 15;
    ull o[4][2];
    #pragma unroll
    for (int u = 0; u < 4; u++) { o[u][0] = 0ull; o[u][1] = 0ull; }

    for (int s0 = 0; s0 < 96; s0 += 4) {
        float pa[4][4];
        #pragma unroll
        for (int u = 0; u < 4; u++)
            *(float4*)&pa[u][0] = *(const float4*)&Ps[qy * 4 + u][s0];
        #pragma unroll
        for (int t = 0; t < 4; t++) {
            ulonglong2 kv = *(const ulonglong2*)&Ks[s0 + t][dx * 4];
            #pragma unroll
            for (int u = 0; u < 4; u++) {
                ull pd = dup2(pa[u][t]);
                fma2(o[u][0], pd, kv.x);
                fma2(o[u][1], pd, kv.y);
            }
        }
    }

    #pragma unroll
    for (int u = 0; u < 4; u++) {
        size_t off = (size_t)(p*1024 + (qy*4 + u)*32 + i) * DDIM + h*64 + dx*4;
        float4 old = *(const float4*)(g_ao + off);
        float2 t0 = unpk(o[u][0]), t1 = unpk(o[u][1]);
        *(float4*)(g_ao + off) = make_float4(old.x + t0.x, old.y + t0.y,
                                             old.z + t1.x, old.w + t1.y);
    }
}

// ---------------------------------------------------------------------------
extern "C" void kernel_launch(void* const* d_in, const int* in_sizes, int n_in,
                              void* d_out, int out_size)
{
    const float* x  = (const float*)d_in[0];
    const float* Wq = (const float*)d_in[1];
    const float* Wo = (const float*)d_in[2];
    const float* bo = (const float*)d_in[3];
    float* out = (float*)d_out;

    float *qp = nullptr, *aop = nullptr;
    cudaGetSymbolAddress((void**)&qp,  g_q);
    cudaGetSymbolAddress((void**)&aop, g_ao);

    const dim3 gridG(512 / BN, ROWS / BM);   // (8, 24)
    const dim3 gridA(32, 8, 3);              // (i|j, head, plane)

    gemm_tf32<<<gridG, 256>>>(x, Wq, nullptr, qp, ROWS, 512, 512);
    k1_scores<<<gridA, 192>>>();
    k2_mid  <<<gridA, 256>>>();
    k3_out  <<<gridA, 128>>>();
    gemm_tf32<<<gridG, 256>>>(aop, Wo, bo, out, ROWS, 512, 512);
}

// round 7
// speedup vs baseline: 2.1301x; 1.7091x over previous
#include <cuda_runtime.h>
#include <cuda_bf16.h>
#include <cstddef>

#define DDIM 512
#define ROWS 3072

__device__ float g_q [ROWS * DDIM];
__device__ float g_ao[ROWS * DDIM];
__device__ float g_S [ROWS * 8 * 128];   // [gq][h][slot]; 0..95 = i/fixed, 96..127 = j-dep

// bf16 split buffers (A reused for x then ao; B for Wq then Wo)
__device__ __align__(16) __nv_bfloat16 g_Ahi[ROWS * DDIM];
__device__ __align__(16) __nv_bfloat16 g_Alo[ROWS * DDIM];
__device__ __align__(16) __nv_bfloat16 g_Bhi[DDIM * DDIM];
__device__ __align__(16) __nv_bfloat16 g_Blo[DDIM * DDIM];

typedef unsigned long long ull;

__device__ __forceinline__ ull dup2(float x) {
    ull r; asm("mov.b64 %0, {%1, %1};" : "=l"(r) : "f"(x)); return r;
}
__device__ __forceinline__ void fma2(ull& d, ull a, ull b) {
    asm("fma.rn.f32x2 %0, %1, %2, %3;" : "=l"(d) : "l"(a), "l"(b), "l"(d));
}
__device__ __forceinline__ float2 unpk(ull v) {
    float2 f; asm("mov.b64 {%0, %1}, %2;" : "=f"(f.x), "=f"(f.y) : "l"(v)); return f;
}

// ---------------------------------------------------------------------------
// split: src fp32 -> hi = bf16(x), lo = bf16(x - hi). 4 elems/thread.
// ---------------------------------------------------------------------------
__global__ __launch_bounds__(256) void split_bf16(
    const float* __restrict__ src,
    __nv_bfloat16* __restrict__ hi, __nv_bfloat16* __restrict__ lo, int n4)
{
    int idx = blockIdx.x * blockDim.x + threadIdx.x;
    if (idx >= n4) return;
    float4 v = ((const float4*)src)[idx];
    __nv_bfloat16 h0 = __float2bfloat16_rn(v.x);
    __nv_bfloat16 h1 = __float2bfloat16_rn(v.y);
    __nv_bfloat16 h2 = __float2bfloat16_rn(v.z);
    __nv_bfloat16 h3 = __float2bfloat16_rn(v.w);
    __nv_bfloat16 l0 = __float2bfloat16_rn(v.x - __bfloat162float(h0));
    __nv_bfloat16 l1 = __float2bfloat16_rn(v.y - __bfloat162float(h1));
    __nv_bfloat16 l2 = __float2bfloat16_rn(v.z - __bfloat162float(h2));
    __nv_bfloat16 l3 = __float2bfloat16_rn(v.w - __bfloat162float(h3));
    ((__nv_bfloat162*)hi)[idx * 2]     = __nv_bfloat162(h0, h1);
    ((__nv_bfloat162*)hi)[idx * 2 + 1] = __nv_bfloat162(h2, h3);
    ((__nv_bfloat162*)lo)[idx * 2]     = __nv_bfloat162(l0, l1);
    ((__nv_bfloat162*)lo)[idx * 2 + 1] = __nv_bfloat162(l2, l3);
}

// ---------------------------------------------------------------------------
// GEMM: C[M,N] = A[M,K] @ B[N,K]^T (+bias), bf16 3-term split, f32 accum.
// BM=BN=64, BK=32; 128 threads = 4 warps (2m x 2n), warp tile 32x32.
// cp.async double-buffered; smem pitch 40 bf16 -> conflict-free ldmatrix/LDS.
// ---------------------------------------------------------------------------
#define PITCH 40

__device__ __forceinline__ void ldm4(unsigned* r, unsigned addr) {
    asm volatile("ldmatrix.sync.aligned.m8n8.x4.shared.b16 {%0,%1,%2,%3}, [%4];"
        : "=r"(r[0]), "=r"(r[1]), "=r"(r[2]), "=r"(r[3]) : "r"(addr));
}
__device__ __forceinline__ void mma_bf16(float* c, const unsigned* a, const unsigned* b) {
    asm volatile(
        "mma.sync.aligned.m16n8k16.row.col.f32.bf16.bf16.f32 "
        "{%0,%1,%2,%3}, {%4,%5,%6,%7}, {%8,%9}, {%0,%1,%2,%3};"
        : "+f"(c[0]), "+f"(c[1]), "+f"(c[2]), "+f"(c[3])
        : "r"(a[0]), "r"(a[1]), "r"(a[2]), "r"(a[3]), "r"(b[0]), "r"(b[1]));
}
__device__ __forceinline__ void cpa16(unsigned saddr, const void* gptr) {
    asm volatile("cp.async.cg.shared.global [%0], [%1], 16;" :: "r"(saddr), "l"(gptr));
}

__global__ __launch_bounds__(128) void gemm_bf16(
    const __nv_bfloat16* __restrict__ Ahi, const __nv_bfloat16* __restrict__ Alo,
    const __nv_bfloat16* __restrict__ Bhi, const __nv_bfloat16* __restrict__ Blo,
    const float* __restrict__ bias, float* __restrict__ C,
    int M, int N, int K)
{
    __shared__ __nv_bfloat16 sA[2][2][64][PITCH];   // [buf][hi/lo][m][k]
    __shared__ __nv_bfloat16 sB[2][2][64][PITCH];

    const int bm = blockIdx.y * 64;
    const int bn = blockIdx.x * 64;
    const int tid  = threadIdx.x;
    const int warp = tid >> 5;
    const int lane = tid & 31;
    const int wm = warp & 1;        // m half
    const int wn = warp >> 1;       // n half

    const int NS = K / 32;

    // staging map: 8 x 16B chunks per thread per stage
    const __nv_bfloat16* gsrc[4] = { Ahi, Alo, Bhi, Blo };

    auto issue = [&](int s) {
        const int k0 = s * 32;
        const int buf = s & 1;
        #pragma unroll
        for (int it = 0; it < 8; it++) {
            int idx = tid + 128 * it;
            int sel = idx >> 8;                // 0..3
            int c   = idx & 255;
            int row = c >> 2, ch = c & 3;
            const __nv_bfloat16* gp = gsrc[sel] +
                (size_t)((sel < 2 ? bm : bn) + row) * K + k0 + ch * 8;
            __nv_bfloat16* sp = (sel < 2)
                ? &sA[buf][sel][row][ch * 8]
                : &sB[buf][sel - 2][row][ch * 8];
            cpa16((unsigned)__cvta_generic_to_shared(sp), gp);
        }
        asm volatile("cp.async.commit_group;");
    };

    float acc[2][4][4];
    #pragma unroll
    for (int mt = 0; mt < 2; mt++)
        #pragma unroll
        for (int nt = 0; nt < 4; nt++)
            #pragma unroll
            for (int u = 0; u < 4; u++) acc[mt][nt][u] = 0.f;

    issue(0);

    for (int s = 0; s < NS; s++) {
        if (s + 1 < NS) {
            issue(s + 1);
            asm volatile("cp.async.wait_group 1;");
        } else {
            asm volatile("cp.async.wait_group 0;");
        }
        __syncthreads();
        const int buf = s & 1;

        #pragma unroll
        for (int kk = 0; kk < 2; kk++) {
            // A fragments via ldmatrix.x4 (conflict-free with PITCH=40)
            unsigned ah[2][4], al[2][4];
            #pragma unroll
            for (int mt = 0; mt < 2; mt++) {
                int row = wm * 32 + mt * 16 + (lane & 15);
                int col = kk * 16 + (lane >> 4) * 8;
                ldm4(ah[mt], (unsigned)__cvta_generic_to_shared(&sA[buf][0][row][col]));
                ldm4(al[mt], (unsigned)__cvta_generic_to_shared(&sA[buf][1][row][col]));
            }
            // B fragments via conflict-free scalar LDS32
            unsigned bh[4][2], bl[4][2];
            #pragma unroll
            for (int nt = 0; nt < 4; nt++) {
                int n = wn * 32 + nt * 8 + (lane >> 2);
                int w0 = kk * 16 + (lane & 3) * 2;
                bh[nt][0] = *(const unsigned*)&sB[buf][0][n][w0];
                bh[nt][1] = *(const unsigned*)&sB[buf][0][n][w0 + 8];
                bl[nt][0] = *(const unsigned*)&sB[buf][1][n][w0];
                bl[nt][1] = *(const unsigned*)&sB[buf][1][n][w0 + 8];
            }
            #pragma unroll
            for (int mt = 0; mt < 2; mt++)
                #pragma unroll
                for (int nt = 0; nt < 4; nt++) {
                    mma_bf16(acc[mt][nt], ah[mt], bl[nt]);   // hi*lo
                    mma_bf16(acc[mt][nt], al[mt], bh[nt]);   // lo*hi
                    mma_bf16(acc[mt][nt], ah[mt], bh[nt]);   // hi*hi
                }
        }
        __syncthreads();
    }

    // epilogue
    const int r4 = lane >> 2;
    const int kq = lane & 3;
    #pragma unroll
    for (int nt = 0; nt < 4; nt++) {
        int col = bn + wn * 32 + nt * 8 + 2 * kq;
        float2 bb = make_float2(0.f, 0.f);
        if (bias) bb = *(const float2*)(bias + col);
        #pragma unroll
        for (int mt = 0; mt < 2; mt++) {
            int row0 = bm + wm * 32 + mt * 16 + r4;
            *(float2*)(C + (size_t)row0 * N + col) =
                make_float2(acc[mt][nt][0] + bb.x, acc[mt][nt][1] + bb.y);
            *(float2*)(C + (size_t)(row0 + 8) * N + col) =
                make_float2(acc[mt][nt][2] + bb.x, acc[mt][nt][3] + bb.y);
        }
    }
}

// ---------------------------------------------------------------------------
// Key index mapping (verified rounds 1-5).
// ---------------------------------------------------------------------------
__device__ __forceinline__ int key_gpos(int p, int f, int i, int j)
{
    const int g = f >> 5;
    const int r = f & 31;
    int pos, sp;
    if (p == 0) {
        sp = (f < 64) ? 1 : 2;
        pos = (g == 0) ? r * 32 + i
            : (g == 1) ? 480 + r
            : (g == 2) ? r * 32 + 15
            :            j * 32 + r;
    } else if (p == 1) {
        sp = (f < 64) ? 0 : 2;
        pos = (g == 0) ? r * 32 + i
            : (g == 1) ? 480 + r
            : (g == 2) ? r * 32 + (31 - j)
            :            480 + r;
    } else {
        sp = (f < 64) ? 0 : 2;
        pos = (g == 0) ? r * 32 + 15
            : (g == 1) ? j * 32 + r
            : (g == 2) ? r * 32 + 15
            :            (31 - i) * 32 + r;
    }
    return sp * 1024 + pos;
}

__device__ __forceinline__ int k1_f(int p, int s)
{
    int g = s >> 5;
    if (g >= 3 - p) g++;
    return g * 32 + (s & 31);
}

// ---------------------------------------------------------------------------
// K1: scores for the 96 i-dep/fixed keys. CTA = (i, h, p); 192 threads.
// ---------------------------------------------------------------------------
__global__ __launch_bounds__(192) void k1_scores()
{
    const int i = blockIdx.x, h = blockIdx.y, p = blockIdx.z;
    const int tid = threadIdx.x;

    __shared__ int   spos[96];
    __shared__ float Ks[64][96];
    __shared__ float Qs[64][32];

    if (tid < 96) spos[tid] = key_gpos(p, k1_f(p, tid), i, 0);
    __syncthreads();

    #pragma unroll
    for (int it = 0; it < 8; it++) {
        int idx = tid + 192 * it;
        int kk = idx % 96, dg = (idx / 96) * 4;
        float4 v = *(const float4*)(g_q + (size_t)spos[kk] * DDIM + h * 64 + dg);
        Ks[dg+0][kk] = v.x; Ks[dg+1][kk] = v.y;
        Ks[dg+2][kk] = v.z; Ks[dg+3][kk] = v.w;
    }
    #pragma unroll
    for (int it = 0; it < 3; it++) {
        int idx = tid + 192 * it;
        if (idx < 512) {
            int q = idx & 31, dg = (idx >> 5) * 4;
            float4 v = *(const float4*)(g_q + (size_t)(p*1024 + q*32 + i) * DDIM + h*64 + dg);
            Qs[dg+0][q] = v.x; Qs[dg+1][q] = v.y;
            Qs[dg+2][q] = v.z; Qs[dg+3][q] = v.w;
        }
    }
    __syncthreads();

    const int qy = tid / 24, fx = tid % 24;
    ull acc[4][2];
    #pragma unroll
    for (int u = 0; u < 4; u++) { acc[u][0] = 0ull; acc[u][1] = 0ull; }

    #pragma unroll 4
    for (int d = 0; d < 64; d++) {
        float4 q4 = *(const float4*)&Qs[d][qy * 4];
        ulonglong2 kv = *(const ulonglong2*)&Ks[d][fx * 4];
        ull qd;
        qd = dup2(q4.x); fma2(acc[0][0], qd, kv.x); fma2(acc[0][1], qd, kv.y);
        qd = dup2(q4.y); fma2(acc[1][0], qd, kv.x); fma2(acc[1][1], qd, kv.y);
        qd = dup2(q4.z); fma2(acc[2][0], qd, kv.x); fma2(acc[2][1], qd, kv.y);
        qd = dup2(q4.w); fma2(acc[3][0], qd, kv.x); fma2(acc[3][1], qd, kv.y);
    }

    #pragma unroll
    for (int u = 0; u < 4; u++) {
        int q = qy * 4 + u;
        size_t base = ((size_t)(p*1024 + q*32 + i) * 8 + h) * 128 + fx * 4;
        float2 e0 = unpk(acc[u][0]);
        float2 e1 = unpk(acc[u][1]);
        *(float4*)(g_S + base) = make_float4(e0.x*0.125f, e0.y*0.125f,
                                             e1.x*0.125f, e1.y*0.125f);
    }
}

// ---------------------------------------------------------------------------
// K2: j-dep scores (slots 96..127) + softmax + j-part of output.
// ---------------------------------------------------------------------------
__global__ __launch_bounds__(256) void k2_mid()
{
    const int j = blockIdx.x, h = blockIdx.y, p = blockIdx.z;
    const int tid = threadIdx.x;
    const int qbase = p * 1024 + j * 32;

    __shared__ int   spos[32];
    __shared__ float Kd[64][32];
    __shared__ float Kf[32][68];
    __shared__ float Qs[64][32];
    __shared__ float Sall[32][132];

    if (tid < 32) spos[tid] = key_gpos(p, (3 - p) * 32 + tid, 0, j);
    __syncthreads();

    #pragma unroll
    for (int it = 0; it < 2; it++) {
        int idx = tid + 256 * it;
        int q = idx & 31, dg = (idx >> 5) * 4;
        float4 v = *(const float4*)(g_q + (size_t)(qbase + q) * DDIM + h * 64 + dg);
        Qs[dg+0][q] = v.x; Qs[dg+1][q] = v.y; Qs[dg+2][q] = v.z; Qs[dg+3][q] = v.w;
        float4 w = *(const float4*)(g_q + (size_t)spos[q] * DDIM + h * 64 + dg);
        Kd[dg+0][q] = w.x; Kd[dg+1][q] = w.y; Kd[dg+2][q] = w.z; Kd[dg+3][q] = w.w;
        *(float4*)&Kf[q][dg] = w;
    }
    #pragma unroll
    for (int it = 0; it < 3; it++) {
        int idx = tid + 256 * it;
        int q = idx / 24, sg = (idx % 24) * 4;
        *(float4*)&Sall[q][sg] =
            *(const float4*)(g_S + ((size_t)(qbase + q) * 8 + h) * 128 + sg);
    }
    __syncthreads();

    {
        const int qy2 = tid >> 4, fx2 = tid & 15;
        ull a0 = 0ull, a1 = 0ull;
        #pragma unroll 8
        for (int d = 0; d < 64; d++) {
            float2 q2 = *(const float2*)&Qs[d][qy2 * 2];
            ull kv = *(const ull*)&Kd[d][fx2 * 2];
            fma2(a0, dup2(q2.x), kv);
            fma2(a1, dup2(q2.y), kv);
        }
        float2 s0 = unpk(a0), s1 = unpk(a1);
        Sall[qy2*2  ][96 + fx2*2]     = s0.x * 0.125f;
        Sall[qy2*2  ][96 + fx2*2 + 1] = s0.y * 0.125f;
        Sall[qy2*2+1][96 + fx2*2]     = s1.x * 0.125f;
        Sall[qy2*2+1][96 + fx2*2 + 1] = s1.y * 0.125f;
    }
    __syncthreads();

    {
        const int qs = tid >> 3, l8 = tid & 7;
        float vals[16];
        float m = -1e30f;
        #pragma unroll
        for (int u = 0; u < 16; u++) {
            vals[u] = Sall[qs][l8 + 8 * u];
            m = fmaxf(m, vals[u]);
        }
        #pragma unroll
        for (int off = 4; off; off >>= 1)
            m = fmaxf(m, __shfl_xor_sync(0xffffffffu, m, off));
        float sum = 0.f;
        #pragma unroll
        for (int u = 0; u < 16; u++) { vals[u] = __expf(vals[u] - m); sum += vals[u]; }
        #pragma unroll
        for (int off = 4; off; off >>= 1)
            sum += __shfl_xor_sync(0xffffffffu, sum, off);
        const float inv = 1.0f / sum;
        #pragma unroll
        for (int u = 0; u < 16; u++)
            Sall[qs][l8 + 8 * u] = vals[u] * inv;
    }
    __syncthreads();

    #pragma unroll
    for (int it = 0; it < 4; it++) {
        int c = tid + 256 * it;
        int q = c >> 5, f4 = (c & 31) * 4;
        *(float4*)(g_S + ((size_t)(qbase + q) * 8 + h) * 128 + f4) =
            *(const float4*)&Sall[q][f4];
    }

    {
        const int qy = tid >> 4, dx = tid & 15;
        ull o00 = 0ull, o01 = 0ull, o10 = 0ull, o11 = 0ull;
        #pragma unroll 8
        for (int r = 0; r < 32; r++) {
            float pa = Sall[qy*2  ][96 + r];
            float pb = Sall[qy*2+1][96 + r];
            ulonglong2 kv = *(const ulonglong2*)&Kf[r][dx * 4];
            ull da = dup2(pa), db = dup2(pb);
            fma2(o00, da, kv.x); fma2(o01, da, kv.y);
            fma2(o10, db, kv.x); fma2(o11, db, kv.y);
        }
        float2 t0 = unpk(o00), t1 = unpk(o01);
        *(float4*)(g_ao + (size_t)(qbase + qy*2) * DDIM + h*64 + dx*4) =
            make_float4(t0.x, t0.y, t1.x, t1.y);
        t0 = unpk(o10); t1 = unpk(o11);
        *(float4*)(g_ao + (size_t)(qbase + qy*2 + 1) * DDIM + h*64 + dx*4) =
            make_float4(t0.x, t0.y, t1.x, t1.y);
    }
}

// ---------------------------------------------------------------------------
// K3: i-part of output. CTA = (i, h, p); 128 threads, 4q x 4d tiles.
// ---------------------------------------------------------------------------
__global__ __launch_bounds__(128) void k3_out()
{
    const int i = blockIdx.x, h = blockIdx.y, p = blockIdx.z;
    const int tid = threadIdx.x;

    __shared__ int   spos[96];
    __shared__ float Ks[96][64];
    __shared__ float Ps[32][100];

    if (tid < 96) spos[tid] = key_gpos(p, k1_f(p, tid), i, 0);
    __syncthreads();

    #pragma unroll
    for (int it = 0; it < 12; it++) {
        int c = tid + 128 * it;
        int key = c >> 4, dg = (c & 15) * 4;
        *(float4*)&Ks[key][dg] =
            *(const float4*)(g_q + (size_t)spos[key] * DDIM + h * 64 + dg);
    }
    #pragma unroll
    for (int it = 0; it < 6; it++) {
        int idx = tid + 128 * it;
        int q = idx / 24, sg = (idx % 24) * 4;
        *(float4*)&Ps[q][sg] =
            *(const float4*)(g_S + ((size_t)(p*1024 + q*32 + i) * 8 + h) * 128 + sg);
    }
    __syncthreads();

    const int qy = tid >> 4, dx = tid & 15;
    ull o[4][2];
    #pragma unroll
    for (int u = 0; u < 4; u++) { o[u][0] = 0ull; o[u][1] = 0ull; }

    for (int s0 = 0; s0 < 96; s0 += 4) {
        float pa[4][4];
        #pragma unroll
        for (int u = 0; u < 4; u++)
            *(float4*)&pa[u][0] = *(const float4*)&Ps[qy * 4 + u][s0];
        #pragma unroll
        for (int t = 0; t < 4; t++) {
            ulonglong2 kv = *(const ulonglong2*)&Ks[s0 + t][dx * 4];
            #pragma unroll
            for (int u = 0; u < 4; u++) {
                ull pd = dup2(pa[u][t]);
                fma2(o[u][0], pd, kv.x);
                fma2(o[u][1], pd, kv.y);
            }
        }
    }

    #pragma unroll
    for (int u = 0; u < 4; u++) {
        size_t off = (size_t)(p*1024 + (qy*4 + u)*32 + i) * DDIM + h*64 + dx*4;
        float4 old = *(const float4*)(g_ao + off);
        float2 t0 = unpk(o[u][0]), t1 = unpk(o[u][1]);
        *(float4*)(g_ao + off) = make_float4(old.x + t0.x, old.y + t0.y,
                                             old.z + t1.x, old.w + t1.y);
    }
}

// ---------------------------------------------------------------------------
extern "C" void kernel_launch(void* const* d_in, const int* in_sizes, int n_in,
                              void* d_out, int out_size)
{
    const float* x  = (const float*)d_in[0];
    const float* Wq = (const float*)d_in[1];
    const float* Wo = (const float*)d_in[2];
    const float* bo = (const float*)d_in[3];
    float* out = (float*)d_out;

    float *aop = nullptr, *qp = nullptr;
    cudaGetSymbolAddress((void**)&qp,  g_q);
    cudaGetSymbolAddress((void**)&aop, g_ao);
    __nv_bfloat16 *ahi, *alo, *bhi, *blo;
    cudaGetSymbolAddress((void**)&ahi, g_Ahi);
    cudaGetSymbolAddress((void**)&alo, g_Alo);
    cudaGetSymbolAddress((void**)&bhi, g_Bhi);
    cudaGetSymbolAddress((void**)&blo, g_Blo);

    const int nx4 = ROWS * DDIM / 4;        // 393216
    const int nw4 = DDIM * DDIM / 4;        // 65536
    const dim3 gridG(512 / 64, ROWS / 64);  // (8, 48)
    const dim3 gridA(32, 8, 3);             // (i|j, head, plane)

    // q = x @ Wq^T (bf16 3-term split)
    split_bf16<<<(nx4 + 255) / 256, 256>>>(x,  ahi, alo, nx4);
    split_bf16<<<(nw4 + 255) / 256, 256>>>(Wq, bhi, blo, nw4);
    gemm_bf16<<<gridG, 128>>>(ahi, alo, bhi, blo, nullptr, qp, ROWS, 512, 512);

    // attention
    k1_scores<<<gridA, 192>>>();
    k2_mid  <<<gridA, 256>>>();
    k3_out  <<<gridA, 128>>>();

    // out = ao @ Wo^T + bo
    split_bf16<<<(nx4 + 255) / 256, 256>>>(aop, ahi, alo, nx4);
    split_bf16<<<(nw4 + 255) / 256, 256>>>(Wo,  bhi, blo, nw4);
    gemm_bf16<<<gridG, 128>>>(ahi, alo, bhi, blo, bo, out, ROWS, 512, 512);
}

// round 8
// speedup vs baseline: 2.3431x; 1.1000x over previous
#include <cuda_runtime.h>
#include <cuda_bf16.h>
#include <cstddef>

#define DDIM 512
#define ROWS 3072

__device__ float g_q [ROWS * DDIM];
__device__ float g_ao[ROWS * DDIM];
__device__ float g_S [ROWS * 8 * 128];   // scores [gq][h][slot]; 0..95 i/fixed, 96..127 j-dep

// bf16 split buffers
__device__ __align__(16) __nv_bfloat16 g_Ahi[ROWS * DDIM];   // x, then ao (written by k3)
__device__ __align__(16) __nv_bfloat16 g_Alo[ROWS * DDIM];
__device__ __align__(16) __nv_bfloat16 g_Bhi[DDIM * DDIM];   // Wq, then Wo
__device__ __align__(16) __nv_bfloat16 g_Blo[DDIM * DDIM];
__device__ __align__(16) __nv_bfloat16 g_qhi[ROWS * DDIM];   // split of q (gemm1 epilogue)
__device__ __align__(16) __nv_bfloat16 g_qlo[ROWS * DDIM];
__device__ __align__(16) __nv_bfloat16 g_Phi[ROWS * 8 * 128]; // split of P (k2)
__device__ __align__(16) __nv_bfloat16 g_Plo[ROWS * 8 * 128];

typedef unsigned long long ull;

__device__ __forceinline__ ull dup2(float x) {
    ull r; asm("mov.b64 %0, {%1, %1};" : "=l"(r) : "f"(x)); return r;
}
__device__ __forceinline__ void fma2(ull& d, ull a, ull b) {
    asm("fma.rn.f32x2 %0, %1, %2, %3;" : "=l"(d) : "l"(a), "l"(b), "l"(d));
}
__device__ __forceinline__ float2 unpk(ull v) {
    float2 f; asm("mov.b64 {%0, %1}, %2;" : "=f"(f.x), "=f"(f.y) : "l"(v)); return f;
}
__device__ __forceinline__ void ldm4(unsigned* r, unsigned addr) {
    asm volatile("ldmatrix.sync.aligned.m8n8.x4.shared.b16 {%0,%1,%2,%3}, [%4];"
        : "=r"(r[0]), "=r"(r[1]), "=r"(r[2]), "=r"(r[3]) : "r"(addr));
}
__device__ __forceinline__ void ldm2t(unsigned* r, unsigned addr) {
    asm volatile("ldmatrix.sync.aligned.m8n8.x2.trans.shared.b16 {%0,%1}, [%2];"
        : "=r"(r[0]), "=r"(r[1]) : "r"(addr));
}
__device__ __forceinline__ void mma_bf16(float* c, const unsigned* a, const unsigned* b) {
    asm volatile(
        "mma.sync.aligned.m16n8k16.row.col.f32.bf16.bf16.f32 "
        "{%0,%1,%2,%3}, {%4,%5,%6,%7}, {%8,%9}, {%0,%1,%2,%3};"
        : "+f"(c[0]), "+f"(c[1]), "+f"(c[2]), "+f"(c[3])
        : "r"(a[0]), "r"(a[1]), "r"(a[2]), "r"(a[3]), "r"(b[0]), "r"(b[1]));
}
__device__ __forceinline__ void cpa16(unsigned saddr, const void* gptr) {
    asm volatile("cp.async.cg.shared.global [%0], [%1], 16;" :: "r"(saddr), "l"(gptr));
}
__device__ __forceinline__ unsigned scvt(const void* p) {
    return (unsigned)__cvta_generic_to_shared(p);
}

// ---------------------------------------------------------------------------
// split: src fp32 -> hi = bf16(x), lo = bf16(x - hi). 4 elems/thread.
// ---------------------------------------------------------------------------
__global__ __launch_bounds__(256) void split_bf16(
    const float* __restrict__ src,
    __nv_bfloat16* __restrict__ hi, __nv_bfloat16* __restrict__ lo, int n4)
{
    int idx = blockIdx.x * blockDim.x + threadIdx.x;
    if (idx >= n4) return;
    float4 v = ((const float4*)src)[idx];
    __nv_bfloat16 h0 = __float2bfloat16_rn(v.x);
    __nv_bfloat16 h1 = __float2bfloat16_rn(v.y);
    __nv_bfloat16 h2 = __float2bfloat16_rn(v.z);
    __nv_bfloat16 h3 = __float2bfloat16_rn(v.w);
    __nv_bfloat16 l0 = __float2bfloat16_rn(v.x - __bfloat162float(h0));
    __nv_bfloat16 l1 = __float2bfloat16_rn(v.y - __bfloat162float(h1));
    __nv_bfloat16 l2 = __float2bfloat16_rn(v.z - __bfloat162float(h2));
    __nv_bfloat16 l3 = __float2bfloat16_rn(v.w - __bfloat162float(h3));
    ((__nv_bfloat162*)hi)[idx * 2]     = __nv_bfloat162(h0, h1);
    ((__nv_bfloat162*)hi)[idx * 2 + 1] = __nv_bfloat162(h2, h3);
    ((__nv_bfloat162*)lo)[idx * 2]     = __nv_bfloat162(l0, l1);
    ((__nv_bfloat162*)lo)[idx * 2 + 1] = __nv_bfloat162(l2, l3);
}

// ---------------------------------------------------------------------------
// GEMM (verified round 7): C = A@B^T (+bias), bf16 3-term split, f32 accum.
// Optionally emits bf16 hi/lo split of C (Chi/Clo non-null).
// ---------------------------------------------------------------------------
#define PITCH 40

__global__ __launch_bounds__(128) void gemm_bf16(
    const __nv_bfloat16* __restrict__ Ahi, const __nv_bfloat16* __restrict__ Alo,
    const __nv_bfloat16* __restrict__ Bhi, const __nv_bfloat16* __restrict__ Blo,
    const float* __restrict__ bias, float* __restrict__ C,
    __nv_bfloat16* __restrict__ Chi, __nv_bfloat16* __restrict__ Clo,
    int M, int N, int K)
{
    __shared__ __nv_bfloat16 sA[2][2][64][PITCH];
    __shared__ __nv_bfloat16 sB[2][2][64][PITCH];

    const int bm = blockIdx.y * 64;
    const int bn = blockIdx.x * 64;
    const int tid  = threadIdx.x;
    const int warp = tid >> 5;
    const int lane = tid & 31;
    const int wm = warp & 1;
    const int wn = warp >> 1;
    const int NS = K / 32;

    const __nv_bfloat16* gsrc[4] = { Ahi, Alo, Bhi, Blo };

    auto issue = [&](int s) {
        const int k0 = s * 32;
        const int buf = s & 1;
        #pragma unroll
        for (int it = 0; it < 8; it++) {
            int idx = tid + 128 * it;
            int sel = idx >> 8;
            int c   = idx & 255;
            int row = c >> 2, ch = c & 3;
            const __nv_bfloat16* gp = gsrc[sel] +
                (size_t)((sel < 2 ? bm : bn) + row) * K + k0 + ch * 8;
            __nv_bfloat16* sp = (sel < 2)
                ? &sA[buf][sel][row][ch * 8]
                : &sB[buf][sel - 2][row][ch * 8];
            cpa16(scvt(sp), gp);
        }
        asm volatile("cp.async.commit_group;");
    };

    float acc[2][4][4];
    #pragma unroll
    for (int mt = 0; mt < 2; mt++)
        #pragma unroll
        for (int nt = 0; nt < 4; nt++)
            #pragma unroll
            for (int u = 0; u < 4; u++) acc[mt][nt][u] = 0.f;

    issue(0);

    for (int s = 0; s < NS; s++) {
        if (s + 1 < NS) { issue(s + 1); asm volatile("cp.async.wait_group 1;"); }
        else            { asm volatile("cp.async.wait_group 0;"); }
        __syncthreads();
        const int buf = s & 1;

        #pragma unroll
        for (int kk = 0; kk < 2; kk++) {
            unsigned ah[2][4], al[2][4];
            #pragma unroll
            for (int mt = 0; mt < 2; mt++) {
                int row = wm * 32 + mt * 16 + (lane & 15);
                int col = kk * 16 + (lane >> 4) * 8;
                ldm4(ah[mt], scvt(&sA[buf][0][row][col]));
                ldm4(al[mt], scvt(&sA[buf][1][row][col]));
            }
            unsigned bh[4][2], bl[4][2];
            #pragma unroll
            for (int nt = 0; nt < 4; nt++) {
                int n = wn * 32 + nt * 8 + (lane >> 2);
                int w0 = kk * 16 + (lane & 3) * 2;
                bh[nt][0] = *(const unsigned*)&sB[buf][0][n][w0];
                bh[nt][1] = *(const unsigned*)&sB[buf][0][n][w0 + 8];
                bl[nt][0] = *(const unsigned*)&sB[buf][1][n][w0];
                bl[nt][1] = *(const unsigned*)&sB[buf][1][n][w0 + 8];
            }
            #pragma unroll
            for (int mt = 0; mt < 2; mt++)
                #pragma unroll
                for (int nt = 0; nt < 4; nt++) {
                    mma_bf16(acc[mt][nt], ah[mt], bl[nt]);
                    mma_bf16(acc[mt][nt], al[mt], bh[nt]);
                    mma_bf16(acc[mt][nt], ah[mt], bh[nt]);
                }
        }
        __syncthreads();
    }

    const int r4 = lane >> 2;
    const int kq = lane & 3;
    #pragma unroll
    for (int nt = 0; nt < 4; nt++) {
        int col = bn + wn * 32 + nt * 8 + 2 * kq;
        float2 bb = make_float2(0.f, 0.f);
        if (bias) bb = *(const float2*)(bias + col);
        #pragma unroll
        for (int mt = 0; mt < 2; mt++) {
            int row0 = bm + wm * 32 + mt * 16 + r4;
            float2 v0 = make_float2(acc[mt][nt][0] + bb.x, acc[mt][nt][1] + bb.y);
            float2 v1 = make_float2(acc[mt][nt][2] + bb.x, acc[mt][nt][3] + bb.y);
            *(float2*)(C + (size_t)row0 * N + col) = v0;
            *(float2*)(C + (size_t)(row0 + 8) * N + col) = v1;
            if (Chi) {
                __nv_bfloat16 h0 = __float2bfloat16_rn(v0.x);
                __nv_bfloat16 h1 = __float2bfloat16_rn(v0.y);
                __nv_bfloat16 h2 = __float2bfloat16_rn(v1.x);
                __nv_bfloat16 h3 = __float2bfloat16_rn(v1.y);
                *(__nv_bfloat162*)(Chi + (size_t)row0 * N + col) = __nv_bfloat162(h0, h1);
                *(__nv_bfloat162*)(Chi + (size_t)(row0 + 8) * N + col) = __nv_bfloat162(h2, h3);
                __nv_bfloat16 l0 = __float2bfloat16_rn(v0.x - __bfloat162float(h0));
                __nv_bfloat16 l1 = __float2bfloat16_rn(v0.y - __bfloat162float(h1));
                __nv_bfloat16 l2 = __float2bfloat16_rn(v1.x - __bfloat162float(h2));
                __nv_bfloat16 l3 = __float2bfloat16_rn(v1.y - __bfloat162float(h3));
                *(__nv_bfloat162*)(Clo + (size_t)row0 * N + col) = __nv_bfloat162(l0, l1);
                *(__nv_bfloat162*)(Clo + (size_t)(row0 + 8) * N + col) = __nv_bfloat162(l2, l3);
            }
        }
    }
}

// ---------------------------------------------------------------------------
// Key index mapping (verified rounds 1-7).
// ---------------------------------------------------------------------------
__device__ __forceinline__ int key_gpos(int p, int f, int i, int j)
{
    const int g = f >> 5;
    const int r = f & 31;
    int pos, sp;
    if (p == 0) {
        sp = (f < 64) ? 1 : 2;
        pos = (g == 0) ? r * 32 + i
            : (g == 1) ? 480 + r
            : (g == 2) ? r * 32 + 15
            :            j * 32 + r;
    } else if (p == 1) {
        sp = (f < 64) ? 0 : 2;
        pos = (g == 0) ? r * 32 + i
            : (g == 1) ? 480 + r
            : (g == 2) ? r * 32 + (31 - j)
            :            480 + r;
    } else {
        sp = (f < 64) ? 0 : 2;
        pos = (g == 0) ? r * 32 + 15
            : (g == 1) ? j * 32 + r
            : (g == 2) ? r * 32 + 15
            :            (31 - i) * 32 + r;
    }
    return sp * 1024 + pos;
}

__device__ __forceinline__ int k1_f(int p, int s)
{
    int g = s >> 5;
    if (g >= 3 - p) g++;
    return g * 32 + (s & 31);
}

// ---------------------------------------------------------------------------
// K1 (MMA): scores for 96 i-dep/fixed keys. CTA=(i,h,p), 128 thr = 4 warps.
// S[32q x 96f] = Q @ K^T, bf16 3-term. Warp w covers slots [24w, 24w+24).
// ---------------------------------------------------------------------------
__global__ __launch_bounds__(128) void k1_scores()
{
    const int i = blockIdx.x, h = blockIdx.y, p = blockIdx.z;
    const int tid = threadIdx.x;
    const int warp = tid >> 5, lane = tid & 31;

    __shared__ int spos[96];
    __shared__ __nv_bfloat16 Qh[32][72], Ql[32][72];
    __shared__ __nv_bfloat16 Kh[96][72], Kl[96][72];

    if (tid < 96) spos[tid] = key_gpos(p, k1_f(p, tid), i, 0);
    __syncthreads();

    #pragma unroll
    for (int it = 0; it < 2; it++) {
        int idx = tid + 128 * it;          // 0..255 (32 rows x 8 chunks)
        int row = idx >> 3, ch = (idx & 7) * 8;
        size_t off = (size_t)(p * 1024 + row * 32 + i) * DDIM + h * 64 + ch;
        *(uint4*)&Qh[row][ch] = *(const uint4*)(g_qhi + off);
        *(uint4*)&Ql[row][ch] = *(const uint4*)(g_qlo + off);
    }
    #pragma unroll
    for (int it = 0; it < 6; it++) {
        int idx = tid + 128 * it;          // 0..767 (96 rows x 8 chunks)
        int row = idx >> 3, ch = (idx & 7) * 8;
        size_t off = (size_t)spos[row] * DDIM + h * 64 + ch;
        *(uint4*)&Kh[row][ch] = *(const uint4*)(g_qhi + off);
        *(uint4*)&Kl[row][ch] = *(const uint4*)(g_qlo + off);
    }
    __syncthreads();

    float acc[2][3][4];
    #pragma unroll
    for (int mt = 0; mt < 2; mt++)
        #pragma unroll
        for (int nt = 0; nt < 3; nt++)
            #pragma unroll
            for (int u = 0; u < 4; u++) acc[mt][nt][u] = 0.f;

    #pragma unroll
    for (int kk = 0; kk < 4; kk++) {
        unsigned ah[2][4], al[2][4];
        const int arow = lane & 15, acol = kk * 16 + (lane >> 4) * 8;
        ldm4(ah[0], scvt(&Qh[arow][acol]));
        ldm4(ah[1], scvt(&Qh[16 + arow][acol]));
        ldm4(al[0], scvt(&Ql[arow][acol]));
        ldm4(al[1], scvt(&Ql[16 + arow][acol]));
        unsigned bh[3][2], bl[3][2];
        #pragma unroll
        for (int nt = 0; nt < 3; nt++) {
            int n = warp * 24 + nt * 8 + (lane >> 2);
            int c0 = kk * 16 + (lane & 3) * 2;
            bh[nt][0] = *(const unsigned*)&Kh[n][c0];
            bh[nt][1] = *(const unsigned*)&Kh[n][c0 + 8];
            bl[nt][0] = *(const unsigned*)&Kl[n][c0];
            bl[nt][1] = *(const unsigned*)&Kl[n][c0 + 8];
        }
        #pragma unroll
        for (int mt = 0; mt < 2; mt++)
            #pragma unroll
            for (int nt = 0; nt < 3; nt++) {
                mma_bf16(acc[mt][nt], ah[mt], bl[nt]);
                mma_bf16(acc[mt][nt], al[mt], bh[nt]);
                mma_bf16(acc[mt][nt], ah[mt], bh[nt]);
            }
    }

    const int r4 = lane >> 2, kq = lane & 3;
    #pragma unroll
    for (int mt = 0; mt < 2; mt++)
        #pragma unroll
        for (int nt = 0; nt < 3; nt++) {
            int slot = warp * 24 + nt * 8 + 2 * kq;
            int q0 = mt * 16 + r4;
            size_t b0 = ((size_t)(p*1024 + q0*32 + i) * 8 + h) * 128 + slot;
            size_t b1 = ((size_t)(p*1024 + (q0+8)*32 + i) * 8 + h) * 128 + slot;
            *(float2*)(g_S + b0) = make_float2(acc[mt][nt][0]*0.125f, acc[mt][nt][1]*0.125f);
            *(float2*)(g_S + b1) = make_float2(acc[mt][nt][2]*0.125f, acc[mt][nt][3]*0.125f);
        }
}

// ---------------------------------------------------------------------------
// K2: j-dep scores + softmax + j-part of output; writes P as bf16 hi/lo.
// ---------------------------------------------------------------------------
__global__ __launch_bounds__(256) void k2_mid()
{
    const int j = blockIdx.x, h = blockIdx.y, p = blockIdx.z;
    const int tid = threadIdx.x;
    const int qbase = p * 1024 + j * 32;

    __shared__ int   spos[32];
    __shared__ float Kd[64][32];
    __shared__ float Kf[32][68];
    __shared__ float Qs[64][32];
    __shared__ float Sall[32][132];

    if (tid < 32) spos[tid] = key_gpos(p, (3 - p) * 32 + tid, 0, j);
    __syncthreads();

    #pragma unroll
    for (int it = 0; it < 2; it++) {
        int idx = tid + 256 * it;
        int q = idx & 31, dg = (idx >> 5) * 4;
        float4 v = *(const float4*)(g_q + (size_t)(qbase + q) * DDIM + h * 64 + dg);
        Qs[dg+0][q] = v.x; Qs[dg+1][q] = v.y; Qs[dg+2][q] = v.z; Qs[dg+3][q] = v.w;
        float4 w = *(const float4*)(g_q + (size_t)spos[q] * DDIM + h * 64 + dg);
        Kd[dg+0][q] = w.x; Kd[dg+1][q] = w.y; Kd[dg+2][q] = w.z; Kd[dg+3][q] = w.w;
        *(float4*)&Kf[q][dg] = w;
    }
    #pragma unroll
    for (int it = 0; it < 3; it++) {
        int idx = tid + 256 * it;
        int q = idx / 24, sg = (idx % 24) * 4;
        *(float4*)&Sall[q][sg] =
            *(const float4*)(g_S + ((size_t)(qbase + q) * 8 + h) * 128 + sg);
    }
    __syncthreads();

    {
        const int qy2 = tid >> 4, fx2 = tid & 15;
        ull a0 = 0ull, a1 = 0ull;
        #pragma unroll 8
        for (int d = 0; d < 64; d++) {
            float2 q2 = *(const float2*)&Qs[d][qy2 * 2];
            ull kv = *(const ull*)&Kd[d][fx2 * 2];
            fma2(a0, dup2(q2.x), kv);
            fma2(a1, dup2(q2.y), kv);
        }
        float2 s0 = unpk(a0), s1 = unpk(a1);
        Sall[qy2*2  ][96 + fx2*2]     = s0.x * 0.125f;
        Sall[qy2*2  ][96 + fx2*2 + 1] = s0.y * 0.125f;
        Sall[qy2*2+1][96 + fx2*2]     = s1.x * 0.125f;
        Sall[qy2*2+1][96 + fx2*2 + 1] = s1.y * 0.125f;
    }
    __syncthreads();

    {
        const int qs = tid >> 3, l8 = tid & 7;
        float vals[16];
        float m = -1e30f;
        #pragma unroll
        for (int u = 0; u < 16; u++) {
            vals[u] = Sall[qs][l8 + 8 * u];
            m = fmaxf(m, vals[u]);
        }
        #pragma unroll
        for (int off = 4; off; off >>= 1)
            m = fmaxf(m, __shfl_xor_sync(0xffffffffu, m, off));
        float sum = 0.f;
        #pragma unroll
        for (int u = 0; u < 16; u++) { vals[u] = __expf(vals[u] - m); sum += vals[u]; }
        #pragma unroll
        for (int off = 4; off; off >>= 1)
            sum += __shfl_xor_sync(0xffffffffu, sum, off);
        const float inv = 1.0f / sum;
        #pragma unroll
        for (int u = 0; u < 16; u++)
            Sall[qs][l8 + 8 * u] = vals[u] * inv;
    }
    __syncthreads();

    // write P (slots 0..95 used by k3) as bf16 hi/lo
    #pragma unroll
    for (int it = 0; it < 3; it++) {
        int idx = tid + 256 * it;              // 0..767: 32q x 24 chunks of 4
        int q = idx / 24, f4 = (idx % 24) * 4;
        float4 v = *(const float4*)&Sall[q][f4];
        size_t off = ((size_t)(qbase + q) * 8 + h) * 128 + f4;
        __nv_bfloat16 h0 = __float2bfloat16_rn(v.x);
        __nv_bfloat16 h1 = __float2bfloat16_rn(v.y);
        __nv_bfloat16 h2 = __float2bfloat16_rn(v.z);
        __nv_bfloat16 h3 = __float2bfloat16_rn(v.w);
        *(__nv_bfloat162*)(g_Phi + off)     = __nv_bfloat162(h0, h1);
        *(__nv_bfloat162*)(g_Phi + off + 2) = __nv_bfloat162(h2, h3);
        __nv_bfloat16 l0 = __float2bfloat16_rn(v.x - __bfloat162float(h0));
        __nv_bfloat16 l1 = __float2bfloat16_rn(v.y - __bfloat162float(h1));
        __nv_bfloat16 l2 = __float2bfloat16_rn(v.z - __bfloat162float(h2));
        __nv_bfloat16 l3 = __float2bfloat16_rn(v.w - __bfloat162float(h3));
        *(__nv_bfloat162*)(g_Plo + off)     = __nv_bfloat162(l0, l1);
        *(__nv_bfloat162*)(g_Plo + off + 2) = __nv_bfloat162(l2, l3);
    }

    // O_j = P_j(32x32) @ K_j(32x64)
    {
        const int qy = tid >> 4, dx = tid & 15;
        ull o00 = 0ull, o01 = 0ull, o10 = 0ull, o11 = 0ull;
        #pragma unroll 8
        for (int r = 0; r < 32; r++) {
            float pa = Sall[qy*2  ][96 + r];
            float pb = Sall[qy*2+1][96 + r];
            ulonglong2 kv = *(const ulonglong2*)&Kf[r][dx * 4];
            ull da = dup2(pa), db = dup2(pb);
            fma2(o00, da, kv.x); fma2(o01, da, kv.y);
            fma2(o10, db, kv.x); fma2(o11, db, kv.y);
        }
        float2 t0 = unpk(o00), t1 = unpk(o01);
        *(float4*)(g_ao + (size_t)(qbase + qy*2) * DDIM + h*64 + dx*4) =
            make_float4(t0.x, t0.y, t1.x, t1.y);
        t0 = unpk(o10); t1 = unpk(o11);
        *(float4*)(g_ao + (size_t)(qbase + qy*2 + 1) * DDIM + h*64 + dx*4) =
            make_float4(t0.x, t0.y, t1.x, t1.y);
    }
}

// ---------------------------------------------------------------------------
// K3 (MMA): O[32q x 64d] = g_ao(j-part) + P(32x96) @ K96(96x64).
// A=P (ldmatrix), B=K^T via ldmatrix.x2.trans from [f][d] storage.
// Epilogue also writes bf16 hi/lo split of the final ao (feeds gemm2).
// ---------------------------------------------------------------------------
__global__ __launch_bounds__(128) void k3_out()
{
    const int i = blockIdx.x, h = blockIdx.y, p = blockIdx.z;
    const int tid = threadIdx.x;
    const int warp = tid >> 5, lane = tid & 31;

    __shared__ int spos[96];
    __shared__ __nv_bfloat16 Ph[32][104], Pl[32][104];
    __shared__ __nv_bfloat16 Kh[96][72],  Kl[96][72];

    if (tid < 96) spos[tid] = key_gpos(p, k1_f(p, tid), i, 0);
    __syncthreads();

    #pragma unroll
    for (int it = 0; it < 3; it++) {
        int idx = tid + 128 * it;          // 0..383: 32 rows x 12 chunks
        int row = idx / 12, ch = (idx % 12) * 8;
        size_t off = ((size_t)(p*1024 + row*32 + i) * 8 + h) * 128 + ch;
        *(uint4*)&Ph[row][ch] = *(const uint4*)(g_Phi + off);
        *(uint4*)&Pl[row][ch] = *(const uint4*)(g_Plo + off);
    }
    #pragma unroll
    for (int it = 0; it < 6; it++) {
        int idx = tid + 128 * it;          // 0..767: 96 rows x 8 chunks
        int row = idx >> 3, ch = (idx & 7) * 8;
        size_t off = (size_t)spos[row] * DDIM + h * 64 + ch;
        *(uint4*)&Kh[row][ch] = *(const uint4*)(g_qhi + off);
        *(uint4*)&Kl[row][ch] = *(const uint4*)(g_qlo + off);
    }
    __syncthreads();

    float acc[2][2][4];
    #pragma unroll
    for (int mt = 0; mt < 2; mt++)
        #pragma unroll
        for (int nt = 0; nt < 2; nt++)
            #pragma unroll
            for (int u = 0; u < 4; u++) acc[mt][nt][u] = 0.f;

    #pragma unroll
    for (int ks = 0; ks < 6; ks++) {
        const int k0 = ks * 16;
        unsigned ah[2][4], al[2][4];
        const int arow = lane & 15, acol = k0 + (lane >> 4) * 8;
        ldm4(ah[0], scvt(&Ph[arow][acol]));
        ldm4(ah[1], scvt(&Ph[16 + arow][acol]));
        ldm4(al[0], scvt(&Pl[arow][acol]));
        ldm4(al[1], scvt(&Pl[16 + arow][acol]));
        unsigned bh[2][2], bl[2][2];
        const int brow = k0 + (lane & 7) + 8 * ((lane >> 3) & 1);
        #pragma unroll
        for (int nt = 0; nt < 2; nt++) {
            int bcol = warp * 16 + nt * 8;
            ldm2t(bh[nt], scvt(&Kh[brow][bcol]));
            ldm2t(bl[nt], scvt(&Kl[brow][bcol]));
        }
        #pragma unroll
        for (int mt = 0; mt < 2; mt++)
            #pragma unroll
            for (int nt = 0; nt < 2; nt++) {
                mma_bf16(acc[mt][nt], ah[mt], bl[nt]);
                mma_bf16(acc[mt][nt], al[mt], bh[nt]);
                mma_bf16(acc[mt][nt], ah[mt], bh[nt]);
            }
    }

    const int r4 = lane >> 2, kq = lane & 3;
    #pragma unroll
    for (int mt = 0; mt < 2; mt++)
        #pragma unroll
        for (int nt = 0; nt < 2; nt++) {
            int d = warp * 16 + nt * 8 + 2 * kq;
            #pragma unroll
            for (int half = 0; half < 2; half++) {
                int q0 = mt * 16 + r4 + half * 8;
                size_t off = (size_t)(p*1024 + q0*32 + i) * DDIM + h*64 + d;
                float2 old = *(const float2*)(g_ao + off);
                float v0 = old.x + acc[mt][nt][half * 2];
                float v1 = old.y + acc[mt][nt][half * 2 + 1];
                __nv_bfloat16 h0 = __float2bfloat16_rn(v0);
                __nv_bfloat16 h1 = __float2bfloat16_rn(v1);
                *(__nv_bfloat162*)(g_Ahi + off) = __nv_bfloat162(h0, h1);
                __nv_bfloat16 l0 = __float2bfloat16_rn(v0 - __bfloat162float(h0));
                __nv_bfloat16 l1 = __float2bfloat16_rn(v1 - __bfloat162float(h1));
                *(__nv_bfloat162*)(g_Alo + off) = __nv_bfloat162(l0, l1);
            }
        }
}

// ---------------------------------------------------------------------------
extern "C" void kernel_launch(void* const* d_in, const int* in_sizes, int n_in,
                              void* d_out, int out_size)
{
    const float* x  = (const float*)d_in[0];
    const float* Wq = (const float*)d_in[1];
    const float* Wo = (const float*)d_in[2];
    const float* bo = (const float*)d_in[3];
    float* out = (float*)d_out;

    float *qp = nullptr;
    cudaGetSymbolAddress((void**)&qp, g_q);
    __nv_bfloat16 *ahi, *alo, *bhi, *blo, *qhi, *qlo;
    cudaGetSymbolAddress((void**)&ahi, g_Ahi);
    cudaGetSymbolAddress((void**)&alo, g_Alo);
    cudaGetSymbolAddress((void**)&bhi, g_Bhi);
    cudaGetSymbolAddress((void**)&blo, g_Blo);
    cudaGetSymbolAddress((void**)&qhi, g_qhi);
    cudaGetSymbolAddress((void**)&qlo, g_qlo);

    const int nx4 = ROWS * DDIM / 4;
    const int nw4 = DDIM * DDIM / 4;
    const dim3 gridG(512 / 64, ROWS / 64);  // (8, 48)
    const dim3 gridA(32, 8, 3);

    // q = x @ Wq^T (also emits bf16 split of q)
    split_bf16<<<(nx4 + 255) / 256, 256>>>(x,  ahi, alo, nx4);
    split_bf16<<<(nw4 + 255) / 256, 256>>>(Wq, bhi, blo, nw4);
    gemm_bf16<<<gridG, 128>>>(ahi, alo, bhi, blo, nullptr, qp, qhi, qlo, ROWS, 512, 512);

    // attention
    k1_scores<<<gridA, 128>>>();
    k2_mid  <<<gridA, 256>>>();
    k3_out  <<<gridA, 128>>>();   // writes bf16 split of ao into g_Ahi/g_Alo

    // out = ao @ Wo^T + bo
    split_bf16<<<(nw4 + 255) / 256, 256>>>(Wo, bhi, blo, nw4);
    gemm_bf16<<<gridG, 128>>>(ahi, alo, bhi, blo, bo, out, nullptr, nullptr, ROWS, 512, 512);
}

// round 9
// speedup vs baseline: 2.8061x; 1.1976x over previous
#include <cuda_runtime.h>
#include <cuda_bf16.h>
#include <cstddef>

#define DDIM 512
#define ROWS 3072

__device__ float g_ao[ROWS * DDIM];
__device__ float g_S [ROWS * 8 * 128];   // scores [gq][h][slot]; 0..95 i/fixed

// bf16 split buffers
__device__ __align__(16) __nv_bfloat16 g_Ahi[ROWS * DDIM];   // x, then ao (k3)
__device__ __align__(16) __nv_bfloat16 g_Alo[ROWS * DDIM];
__device__ __align__(16) __nv_bfloat16 g_Bhi[DDIM * DDIM];   // Wq
__device__ __align__(16) __nv_bfloat16 g_Blo[DDIM * DDIM];
__device__ __align__(16) __nv_bfloat16 g_B2hi[DDIM * DDIM];  // Wo
__device__ __align__(16) __nv_bfloat16 g_B2lo[DDIM * DDIM];
__device__ __align__(16) __nv_bfloat16 g_qhi[ROWS * DDIM];   // split of q
__device__ __align__(16) __nv_bfloat16 g_qlo[ROWS * DDIM];
__device__ __align__(16) __nv_bfloat16 g_Phi[ROWS * 8 * 128]; // split of P
__device__ __align__(16) __nv_bfloat16 g_Plo[ROWS * 8 * 128];

__device__ __forceinline__ void ldm4(unsigned* r, unsigned addr) {
    asm volatile("ldmatrix.sync.aligned.m8n8.x4.shared.b16 {%0,%1,%2,%3}, [%4];"
        : "=r"(r[0]), "=r"(r[1]), "=r"(r[2]), "=r"(r[3]) : "r"(addr));
}
__device__ __forceinline__ void ldm2t(unsigned* r, unsigned addr) {
    asm volatile("ldmatrix.sync.aligned.m8n8.x2.trans.shared.b16 {%0,%1}, [%2];"
        : "=r"(r[0]), "=r"(r[1]) : "r"(addr));
}
__device__ __forceinline__ void mma_bf16(float* c, const unsigned* a, const unsigned* b) {
    asm volatile(
        "mma.sync.aligned.m16n8k16.row.col.f32.bf16.bf16.f32 "
        "{%0,%1,%2,%3}, {%4,%5,%6,%7}, {%8,%9}, {%0,%1,%2,%3};"
        : "+f"(c[0]), "+f"(c[1]), "+f"(c[2]), "+f"(c[3])
        : "r"(a[0]), "r"(a[1]), "r"(a[2]), "r"(a[3]), "r"(b[0]), "r"(b[1]));
}
__device__ __forceinline__ void cpa16(unsigned saddr, const void* gptr) {
    asm volatile("cp.async.cg.shared.global [%0], [%1], 16;" :: "r"(saddr), "l"(gptr));
}
__device__ __forceinline__ unsigned scvt(const void* p) {
    return (unsigned)__cvta_generic_to_shared(p);
}
__device__ __forceinline__ void split8(const float* s, __nv_bfloat16* hi, __nv_bfloat16* lo) {
    __nv_bfloat162 H[4], L[4];
    #pragma unroll
    for (int u = 0; u < 4; u++) {
        __nv_bfloat16 h0 = __float2bfloat16_rn(s[2*u]);
        __nv_bfloat16 h1 = __float2bfloat16_rn(s[2*u+1]);
        H[u] = __nv_bfloat162(h0, h1);
        L[u] = __nv_bfloat162(__float2bfloat16_rn(s[2*u]   - __bfloat162float(h0)),
                              __float2bfloat16_rn(s[2*u+1] - __bfloat162float(h1)));
    }
    *(uint4*)hi = *(const uint4*)H;
    *(uint4*)lo = *(const uint4*)L;
}

#define NX4 (ROWS * DDIM / 4)
#define NW4 (DDIM * DDIM / 4)

// ---------------------------------------------------------------------------
// Fused split: x -> Ahi/Alo, Wq -> Bhi/Blo, Wo -> B2hi/B2lo.
// ---------------------------------------------------------------------------
__global__ __launch_bounds__(256) void split_all(
    const float* __restrict__ x, const float* __restrict__ Wq,
    const float* __restrict__ Wo)
{
    int idx = blockIdx.x * 256 + threadIdx.x;
    const float* src; __nv_bfloat16 *hi, *lo; int b;
    if (idx < NX4)            { src = x;  hi = g_Ahi;  lo = g_Alo;  b = idx; }
    else if (idx < NX4 + NW4) { src = Wq; hi = g_Bhi;  lo = g_Blo;  b = idx - NX4; }
    else                      { src = Wo; hi = g_B2hi; lo = g_B2lo; b = idx - NX4 - NW4; }
    float4 v = ((const float4*)src)[b];
    float vv[8]; // unused upper half; reuse split8 on 4+pad style: do directly
    __nv_bfloat16 h0 = __float2bfloat16_rn(v.x);
    __nv_bfloat16 h1 = __float2bfloat16_rn(v.y);
    __nv_bfloat16 h2 = __float2bfloat16_rn(v.z);
    __nv_bfloat16 h3 = __float2bfloat16_rn(v.w);
    ((__nv_bfloat162*)hi)[b*2]   = __nv_bfloat162(h0, h1);
    ((__nv_bfloat162*)hi)[b*2+1] = __nv_bfloat162(h2, h3);
    ((__nv_bfloat162*)lo)[b*2]   = __nv_bfloat162(
        __float2bfloat16_rn(v.x - __bfloat162float(h0)),
        __float2bfloat16_rn(v.y - __bfloat162float(h1)));
    ((__nv_bfloat162*)lo)[b*2+1] = __nv_bfloat162(
        __float2bfloat16_rn(v.z - __bfloat162float(h2)),
        __float2bfloat16_rn(v.w - __bfloat162float(h3)));
    (void)vv;
}

// ---------------------------------------------------------------------------
// GEMM (verified r7/r8): C = A@B^T (+bias), bf16 3-term, f32 accum.
// C may be null (skip fp32 store); Chi/Clo optional bf16 split output.
// ---------------------------------------------------------------------------
#define PITCH 40

__global__ __launch_bounds__(128) void gemm_bf16(
    const __nv_bfloat16* __restrict__ Ahi, const __nv_bfloat16* __restrict__ Alo,
    const __nv_bfloat16* __restrict__ Bhi, const __nv_bfloat16* __restrict__ Blo,
    const float* __restrict__ bias, float* __restrict__ C,
    __nv_bfloat16* __restrict__ Chi, __nv_bfloat16* __restrict__ Clo,
    int M, int N, int K)
{
    __shared__ __nv_bfloat16 sA[2][2][64][PITCH];
    __shared__ __nv_bfloat16 sB[2][2][64][PITCH];

    const int bm = blockIdx.y * 64;
    const int bn = blockIdx.x * 64;
    const int tid  = threadIdx.x;
    const int warp = tid >> 5;
    const int lane = tid & 31;
    const int wm = warp & 1;
    const int wn = warp >> 1;
    const int NS = K / 32;

    const __nv_bfloat16* gsrc[4] = { Ahi, Alo, Bhi, Blo };

    auto issue = [&](int s) {
        const int k0 = s * 32;
        const int buf = s & 1;
        #pragma unroll
        for (int it = 0; it < 8; it++) {
            int idx = tid + 128 * it;
            int sel = idx >> 8;
            int c   = idx & 255;
            int row = c >> 2, ch = c & 3;
            const __nv_bfloat16* gp = gsrc[sel] +
                (size_t)((sel < 2 ? bm : bn) + row) * K + k0 + ch * 8;
            __nv_bfloat16* sp = (sel < 2)
                ? &sA[buf][sel][row][ch * 8]
                : &sB[buf][sel - 2][row][ch * 8];
            cpa16(scvt(sp), gp);
        }
        asm volatile("cp.async.commit_group;");
    };

    float acc[2][4][4];
    #pragma unroll
    for (int mt = 0; mt < 2; mt++)
        #pragma unroll
        for (int nt = 0; nt < 4; nt++)
            #pragma unroll
            for (int u = 0; u < 4; u++) acc[mt][nt][u] = 0.f;

    issue(0);

    for (int s = 0; s < NS; s++) {
        if (s + 1 < NS) { issue(s + 1); asm volatile("cp.async.wait_group 1;"); }
        else            { asm volatile("cp.async.wait_group 0;"); }
        __syncthreads();
        const int buf = s & 1;

        #pragma unroll
        for (int kk = 0; kk < 2; kk++) {
            unsigned ah[2][4], al[2][4];
            #pragma unroll
            for (int mt = 0; mt < 2; mt++) {
                int row = wm * 32 + mt * 16 + (lane & 15);
                int col = kk * 16 + (lane >> 4) * 8;
                ldm4(ah[mt], scvt(&sA[buf][0][row][col]));
                ldm4(al[mt], scvt(&sA[buf][1][row][col]));
            }
            unsigned bh[4][2], bl[4][2];
            #pragma unroll
            for (int nt = 0; nt < 4; nt++) {
                int n = wn * 32 + nt * 8 + (lane >> 2);
                int w0 = kk * 16 + (lane & 3) * 2;
                bh[nt][0] = *(const unsigned*)&sB[buf][0][n][w0];
                bh[nt][1] = *(const unsigned*)&sB[buf][0][n][w0 + 8];
                bl[nt][0] = *(const unsigned*)&sB[buf][1][n][w0];
                bl[nt][1] = *(const unsigned*)&sB[buf][1][n][w0 + 8];
            }
            #pragma unroll
            for (int mt = 0; mt < 2; mt++)
                #pragma unroll
                for (int nt = 0; nt < 4; nt++) {
                    mma_bf16(acc[mt][nt], ah[mt], bl[nt]);
                    mma_bf16(acc[mt][nt], al[mt], bh[nt]);
                    mma_bf16(acc[mt][nt], ah[mt], bh[nt]);
                }
        }
        __syncthreads();
    }

    const int r4 = lane >> 2;
    const int kq = lane & 3;
    #pragma unroll
    for (int nt = 0; nt < 4; nt++) {
        int col = bn + wn * 32 + nt * 8 + 2 * kq;
        float2 bb = make_float2(0.f, 0.f);
        if (bias) bb = *(const float2*)(bias + col);
        #pragma unroll
        for (int mt = 0; mt < 2; mt++) {
            int row0 = bm + wm * 32 + mt * 16 + r4;
            float2 v0 = make_float2(acc[mt][nt][0] + bb.x, acc[mt][nt][1] + bb.y);
            float2 v1 = make_float2(acc[mt][nt][2] + bb.x, acc[mt][nt][3] + bb.y);
            if (C) {
                *(float2*)(C + (size_t)row0 * N + col) = v0;
                *(float2*)(C + (size_t)(row0 + 8) * N + col) = v1;
            }
            if (Chi) {
                __nv_bfloat16 h0 = __float2bfloat16_rn(v0.x);
                __nv_bfloat16 h1 = __float2bfloat16_rn(v0.y);
                __nv_bfloat16 h2 = __float2bfloat16_rn(v1.x);
                __nv_bfloat16 h3 = __float2bfloat16_rn(v1.y);
                *(__nv_bfloat162*)(Chi + (size_t)row0 * N + col) = __nv_bfloat162(h0, h1);
                *(__nv_bfloat162*)(Chi + (size_t)(row0 + 8) * N + col) = __nv_bfloat162(h2, h3);
                *(__nv_bfloat162*)(Clo + (size_t)row0 * N + col) = __nv_bfloat162(
                    __float2bfloat16_rn(v0.x - __bfloat162float(h0)),
                    __float2bfloat16_rn(v0.y - __bfloat162float(h1)));
                *(__nv_bfloat162*)(Clo + (size_t)(row0 + 8) * N + col) = __nv_bfloat162(
                    __float2bfloat16_rn(v1.x - __bfloat162float(h2)),
                    __float2bfloat16_rn(v1.y - __bfloat162float(h3)));
            }
        }
    }
}

// ---------------------------------------------------------------------------
// Key index mapping (verified rounds 1-8).
// ---------------------------------------------------------------------------
__device__ __forceinline__ int key_gpos(int p, int f, int i, int j)
{
    const int g = f >> 5;
    const int r = f & 31;
    int pos, sp;
    if (p == 0) {
        sp = (f < 64) ? 1 : 2;
        pos = (g == 0) ? r * 32 + i
            : (g == 1) ? 480 + r
            : (g == 2) ? r * 32 + 15
            :            j * 32 + r;
    } else if (p == 1) {
        sp = (f < 64) ? 0 : 2;
        pos = (g == 0) ? r * 32 + i
            : (g == 1) ? 480 + r
            : (g == 2) ? r * 32 + (31 - j)
            :            480 + r;
    } else {
        sp = (f < 64) ? 0 : 2;
        pos = (g == 0) ? r * 32 + 15
            : (g == 1) ? j * 32 + r
            : (g == 2) ? r * 32 + 15
            :            (31 - i) * 32 + r;
    }
    return sp * 1024 + pos;
}

__device__ __forceinline__ int k1_f(int p, int s)
{
    int g = s >> 5;
    if (g >= 3 - p) g++;
    return g * 32 + (s & 31);
}

// ---------------------------------------------------------------------------
// K1 (verified r8, staging now cp.async): scores for 96 i-dep/fixed keys.
// ---------------------------------------------------------------------------
__global__ __launch_bounds__(128) void k1_scores()
{
    const int i = blockIdx.x, h = blockIdx.y, p = blockIdx.z;
    const int tid = threadIdx.x;
    const int warp = tid >> 5, lane = tid & 31;

    __shared__ int spos[96];
    __shared__ __nv_bfloat16 Qh[32][72], Ql[32][72];
    __shared__ __nv_bfloat16 Kh[96][72], Kl[96][72];

    if (tid < 96) spos[tid] = key_gpos(p, k1_f(p, tid), i, 0);
    __syncthreads();

    #pragma unroll
    for (int it = 0; it < 2; it++) {
        int idx = tid + 128 * it;
        int row = idx >> 3, ch = (idx & 7) * 8;
        size_t off = (size_t)(p * 1024 + row * 32 + i) * DDIM + h * 64 + ch;
        cpa16(scvt(&Qh[row][ch]), g_qhi + off);
        cpa16(scvt(&Ql[row][ch]), g_qlo + off);
    }
    #pragma unroll
    for (int it = 0; it < 6; it++) {
        int idx = tid + 128 * it;
        int row = idx >> 3, ch = (idx & 7) * 8;
        size_t off = (size_t)spos[row] * DDIM + h * 64 + ch;
        cpa16(scvt(&Kh[row][ch]), g_qhi + off);
        cpa16(scvt(&Kl[row][ch]), g_qlo + off);
    }
    asm volatile("cp.async.commit_group;");
    asm volatile("cp.async.wait_group 0;");
    __syncthreads();

    float acc[2][3][4];
    #pragma unroll
    for (int mt = 0; mt < 2; mt++)
        #pragma unroll
        for (int nt = 0; nt < 3; nt++)
            #pragma unroll
            for (int u = 0; u < 4; u++) acc[mt][nt][u] = 0.f;

    #pragma unroll
    for (int kk = 0; kk < 4; kk++) {
        unsigned ah[2][4], al[2][4];
        const int arow = lane & 15, acol = kk * 16 + (lane >> 4) * 8;
        ldm4(ah[0], scvt(&Qh[arow][acol]));
        ldm4(ah[1], scvt(&Qh[16 + arow][acol]));
        ldm4(al[0], scvt(&Ql[arow][acol]));
        ldm4(al[1], scvt(&Ql[16 + arow][acol]));
        unsigned bh[3][2], bl[3][2];
        #pragma unroll
        for (int nt = 0; nt < 3; nt++) {
            int n = warp * 24 + nt * 8 + (lane >> 2);
            int c0 = kk * 16 + (lane & 3) * 2;
            bh[nt][0] = *(const unsigned*)&Kh[n][c0];
            bh[nt][1] = *(const unsigned*)&Kh[n][c0 + 8];
            bl[nt][0] = *(const unsigned*)&Kl[n][c0];
            bl[nt][1] = *(const unsigned*)&Kl[n][c0 + 8];
        }
        #pragma unroll
        for (int mt = 0; mt < 2; mt++)
            #pragma unroll
            for (int nt = 0; nt < 3; nt++) {
                mma_bf16(acc[mt][nt], ah[mt], bl[nt]);
                mma_bf16(acc[mt][nt], al[mt], bh[nt]);
                mma_bf16(acc[mt][nt], ah[mt], bh[nt]);
            }
    }

    const int r4 = lane >> 2, kq = lane & 3;
    #pragma unroll
    for (int mt = 0; mt < 2; mt++)
        #pragma unroll
        for (int nt = 0; nt < 3; nt++) {
            int slot = warp * 24 + nt * 8 + 2 * kq;
            int q0 = mt * 16 + r4;
            size_t b0 = ((size_t)(p*1024 + q0*32 + i) * 8 + h) * 128 + slot;
            size_t b1 = ((size_t)(p*1024 + (q0+8)*32 + i) * 8 + h) * 128 + slot;
            *(float2*)(g_S + b0) = make_float2(acc[mt][nt][0]*0.125f, acc[mt][nt][1]*0.125f);
            *(float2*)(g_S + b1) = make_float2(acc[mt][nt][2]*0.125f, acc[mt][nt][3]*0.125f);
        }
}

// ---------------------------------------------------------------------------
// K2 (MMA rewrite): j-dep scores + softmax + P split + O_j, all tensor-core.
// CTA = (j, h, p); 128 threads = 4 warps.
// ---------------------------------------------------------------------------
__global__ __launch_bounds__(128) void k2_mid()
{
    const int j = blockIdx.x, h = blockIdx.y, p = blockIdx.z;
    const int tid = threadIdx.x;
    const int warp = tid >> 5, lane = tid & 31;
    const int qbase = p * 1024 + j * 32;

    __shared__ int spos[32];
    __shared__ __nv_bfloat16 Qh[32][72], Ql[32][72];
    __shared__ __nv_bfloat16 Kh[32][72], Kl[32][72];
    __shared__ float Sall[32][132];
    __shared__ __nv_bfloat16 Pjh[32][40], Pjl[32][40];

    if (tid < 32) spos[tid] = key_gpos(p, (3 - p) * 32 + tid, 0, j);
    __syncthreads();

    // staging: Q rows, j-key rows (bf16 hi/lo), fixed scores (fp32)
    #pragma unroll
    for (int it = 0; it < 2; it++) {
        int idx = tid + 128 * it;          // 0..255
        int row = idx >> 3, ch = (idx & 7) * 8;
        size_t qo = (size_t)(qbase + row) * DDIM + h * 64 + ch;
        cpa16(scvt(&Qh[row][ch]), g_qhi + qo);
        cpa16(scvt(&Ql[row][ch]), g_qlo + qo);
        size_t ko = (size_t)spos[row] * DDIM + h * 64 + ch;
        cpa16(scvt(&Kh[row][ch]), g_qhi + ko);
        cpa16(scvt(&Kl[row][ch]), g_qlo + ko);
    }
    #pragma unroll
    for (int it = 0; it < 6; it++) {
        int idx = tid + 128 * it;          // 0..767
        int q = idx / 24, sg = (idx % 24) * 4;
        cpa16(scvt(&Sall[q][sg]), g_S + ((size_t)(qbase + q) * 8 + h) * 128 + sg);
    }
    asm volatile("cp.async.commit_group;");
    asm volatile("cp.async.wait_group 0;");
    __syncthreads();

    const int r4 = lane >> 2, kq = lane & 3;

    // scores: S_j(32q x 32f) = Q @ Kj^T; warp covers 8 f
    {
        float sacc[2][4];
        #pragma unroll
        for (int mt = 0; mt < 2; mt++)
            #pragma unroll
            for (int u = 0; u < 4; u++) sacc[mt][u] = 0.f;

        #pragma unroll
        for (int kk = 0; kk < 4; kk++) {
            unsigned ah[2][4], al[2][4];
            const int arow = lane & 15, acol = kk * 16 + (lane >> 4) * 8;
            ldm4(ah[0], scvt(&Qh[arow][acol]));
            ldm4(ah[1], scvt(&Qh[16 + arow][acol]));
            ldm4(al[0], scvt(&Ql[arow][acol]));
            ldm4(al[1], scvt(&Ql[16 + arow][acol]));
            unsigned bh[2], bl[2];
            int n = warp * 8 + (lane >> 2);
            int c0 = kk * 16 + (lane & 3) * 2;
            bh[0] = *(const unsigned*)&Kh[n][c0];
            bh[1] = *(const unsigned*)&Kh[n][c0 + 8];
            bl[0] = *(const unsigned*)&Kl[n][c0];
            bl[1] = *(const unsigned*)&Kl[n][c0 + 8];
            #pragma unroll
            for (int mt = 0; mt < 2; mt++) {
                mma_bf16(sacc[mt], ah[mt], bl);
                mma_bf16(sacc[mt], al[mt], bh);
                mma_bf16(sacc[mt], ah[mt], bh);
            }
        }
        #pragma unroll
        for (int mt = 0; mt < 2; mt++) {
            int q0 = mt * 16 + r4;
            int f = 96 + warp * 8 + 2 * kq;
            Sall[q0][f]     = sacc[mt][0] * 0.125f;
            Sall[q0][f + 1] = sacc[mt][1] * 0.125f;
            Sall[q0 + 8][f]     = sacc[mt][2] * 0.125f;
            Sall[q0 + 8][f + 1] = sacc[mt][3] * 0.125f;
        }
    }
    __syncthreads();

    // softmax over 128 slots: 4 lanes per query, 32 vals each
    {
        const int qs = tid >> 2, l4 = tid & 3;
        float vals[32];
        float m = -1e30f;
        #pragma unroll
        for (int u = 0; u < 32; u++) {
            vals[u] = Sall[qs][l4 + 4 * u];
            m = fmaxf(m, vals[u]);
        }
        m = fmaxf(m, __shfl_xor_sync(0xffffffffu, m, 2));
        m = fmaxf(m, __shfl_xor_sync(0xffffffffu, m, 1));
        float sum = 0.f;
        #pragma unroll
        for (int u = 0; u < 32; u++) { vals[u] = __expf(vals[u] - m); sum += vals[u]; }
        sum += __shfl_xor_sync(0xffffffffu, sum, 2);
        sum += __shfl_xor_sync(0xffffffffu, sum, 1);
        const float inv = 1.0f / sum;
        #pragma unroll
        for (int u = 0; u < 32; u++)
            Sall[qs][l4 + 4 * u] = vals[u] * inv;
    }
    __syncthreads();

    // P slots 0..95 -> g_Phi/g_Plo; slots 96..127 -> Pjh/Pjl smem
    #pragma unroll
    for (int it = 0; it < 3; it++) {
        int idx = tid + 128 * it;          // 0..383: 32q x 12 chunks of 8
        int q = idx / 12, c = (idx % 12) * 8;
        size_t off = ((size_t)(qbase + q) * 8 + h) * 128 + c;
        split8(&Sall[q][c], g_Phi + off, g_Plo + off);
    }
    {
        int q = tid >> 2, c = (tid & 3) * 8;   // 32q x 4 chunks of 8
        split8(&Sall[q][96 + c], &Pjh[q][c], &Pjl[q][c]);
    }
    __syncthreads();

    // O_j(32q x 64d) = P_j(32x32) @ K_j(32x64); warp covers 16 d
    {
        float oacc[2][2][4];
        #pragma unroll
        for (int mt = 0; mt < 2; mt++)
            #pragma unroll
            for (int nt = 0; nt < 2; nt++)
                #pragma unroll
                for (int u = 0; u < 4; u++) oacc[mt][nt][u] = 0.f;

        #pragma unroll
        for (int ks = 0; ks < 2; ks++) {
            const int k0 = ks * 16;
            unsigned ah[2][4], al[2][4];
            const int arow = lane & 15, acol = k0 + (lane >> 4) * 8;
            ldm4(ah[0], scvt(&Pjh[arow][acol]));
            ldm4(ah[1], scvt(&Pjh[16 + arow][acol]));
            ldm4(al[0], scvt(&Pjl[arow][acol]));
            ldm4(al[1], scvt(&Pjl[16 + arow][acol]));
            unsigned bh[2][2], bl[2][2];
            const int brow = k0 + (lane & 7) + 8 * ((lane >> 3) & 1);
            #pragma unroll
            for (int nt = 0; nt < 2; nt++) {
                int bcol = warp * 16 + nt * 8;
                ldm2t(bh[nt], scvt(&Kh[brow][bcol]));
                ldm2t(bl[nt], scvt(&Kl[brow][bcol]));
            }
            #pragma unroll
            for (int mt = 0; mt < 2; mt++)
                #pragma unroll
                for (int nt = 0; nt < 2; nt++) {
                    mma_bf16(oacc[mt][nt], ah[mt], bl[nt]);
                    mma_bf16(oacc[mt][nt], al[mt], bh[nt]);
                    mma_bf16(oacc[mt][nt], ah[mt], bh[nt]);
                }
        }
        #pragma unroll
        for (int mt = 0; mt < 2; mt++)
            #pragma unroll
            for (int nt = 0; nt < 2; nt++) {
                int d = warp * 16 + nt * 8 + 2 * kq;
                #pragma unroll
                for (int half = 0; half < 2; half++) {
                    int q0 = mt * 16 + r4 + half * 8;
                    *(float2*)(g_ao + (size_t)(qbase + q0) * DDIM + h * 64 + d) =
                        make_float2(oacc[mt][nt][half*2], oacc[mt][nt][half*2+1]);
                }
            }
    }
}

// ---------------------------------------------------------------------------
// K3 (verified r8, staging now cp.async): O += P96 @ K96; writes bf16 ao split.
// ---------------------------------------------------------------------------
__global__ __launch_bounds__(128) void k3_out()
{
    const int i = blockIdx.x, h = blockIdx.y, p = blockIdx.z;
    const int tid = threadIdx.x;
    const int warp = tid >> 5, lane = tid & 31;

    __shared__ int spos[96];
    __shared__ __nv_bfloat16 Ph[32][104], Pl[32][104];
    __shared__ __nv_bfloat16 Kh[96][72],  Kl[96][72];

    if (tid < 96) spos[tid] = key_gpos(p, k1_f(p, tid), i, 0);
    __syncthreads();

    #pragma unroll
    for (int it = 0; it < 3; it++) {
        int idx = tid + 128 * it;
        int row = idx / 12, ch = (idx % 12) * 8;
        size_t off = ((size_t)(p*1024 + row*32 + i) * 8 + h) * 128 + ch;
        cpa16(scvt(&Ph[row][ch]), g_Phi + off);
        cpa16(scvt(&Pl[row][ch]), g_Plo + off);
    }
    #pragma unroll
    for (int it = 0; it < 6; it++) {
        int idx = tid + 128 * it;
        int row = idx >> 3, ch = (idx & 7) * 8;
        size_t off = (size_t)spos[row] * DDIM + h * 64 + ch;
        cpa16(scvt(&Kh[row][ch]), g_qhi + off);
        cpa16(scvt(&Kl[row][ch]), g_qlo + off);
    }
    asm volatile("cp.async.commit_group;");
    asm volatile("cp.async.wait_group 0;");
    __syncthreads();

    float acc[2][2][4];
    #pragma unroll
    for (int mt = 0; mt < 2; mt++)
        #pragma unroll
        for (int nt = 0; nt < 2; nt++)
            #pragma unroll
            for (int u = 0; u < 4; u++) acc[mt][nt][u] = 0.f;

    #pragma unroll
    for (int ks = 0; ks < 6; ks++) {
        const int k0 = ks * 16;
        unsigned ah[2][4], al[2][4];
        const int arow = lane & 15, acol = k0 + (lane >> 4) * 8;
        ldm4(ah[0], scvt(&Ph[arow][acol]));
        ldm4(ah[1], scvt(&Ph[16 + arow][acol]));
        ldm4(al[0], scvt(&Pl[arow][acol]));
        ldm4(al[1], scvt(&Pl[16 + arow][acol]));
        unsigned bh[2][2], bl[2][2];
        const int brow = k0 + (lane & 7) + 8 * ((lane >> 3) & 1);
        #pragma unroll
        for (int nt = 0; nt < 2; nt++) {
            int bcol = warp * 16 + nt * 8;
            ldm2t(bh[nt], scvt(&Kh[brow][bcol]));
            ldm2t(bl[nt], scvt(&Kl[brow][bcol]));
        }
        #pragma unroll
        for (int mt = 0; mt < 2; mt++)
            #pragma unroll
            for (int nt = 0; nt < 2; nt++) {
                mma_bf16(acc[mt][nt], ah[mt], bl[nt]);
                mma_bf16(acc[mt][nt], al[mt], bh[nt]);
                mma_bf16(acc[mt][nt], ah[mt], bh[nt]);
            }
    }

    const int r4 = lane >> 2, kq = lane & 3;
    #pragma unroll
    for (int mt = 0; mt < 2; mt++)
        #pragma unroll
        for (int nt = 0; nt < 2; nt++) {
            int d = warp * 16 + nt * 8 + 2 * kq;
            #pragma unroll
            for (int half = 0; half < 2; half++) {
                int q0 = mt * 16 + r4 + half * 8;
                size_t off = (size_t)(p*1024 + q0*32 + i) * DDIM + h*64 + d;
                float2 old = *(const float2*)(g_ao + off);
                float v0 = old.x + acc[mt][nt][half * 2];
                float v1 = old.y + acc[mt][nt][half * 2 + 1];
                __nv_bfloat16 h0 = __float2bfloat16_rn(v0);
                __nv_bfloat16 h1 = __float2bfloat16_rn(v1);
                *(__nv_bfloat162*)(g_Ahi + off) = __nv_bfloat162(h0, h1);
                *(__nv_bfloat162*)(g_Alo + off) = __nv_bfloat162(
                    __float2bfloat16_rn(v0 - __bfloat162float(h0)),
                    __float2bfloat16_rn(v1 - __bfloat162float(h1)));
            }
        }
}

// ---------------------------------------------------------------------------
extern "C" void kernel_launch(void* const* d_in, const int* in_sizes, int n_in,
                              void* d_out, int out_size)
{
    const float* x  = (const float*)d_in[0];
    const float* Wq = (const float*)d_in[1];
    const float* Wo = (const float*)d_in[2];
    const float* bo = (const float*)d_in[3];
    float* out = (float*)d_out;

    __nv_bfloat16 *ahi, *alo, *bhi, *blo, *b2hi, *b2lo, *qhi, *qlo;
    cudaGetSymbolAddress((void**)&ahi,  g_Ahi);
    cudaGetSymbolAddress((void**)&alo,  g_Alo);
    cudaGetSymbolAddress((void**)&bhi,  g_Bhi);
    cudaGetSymbolAddress((void**)&blo,  g_Blo);
    cudaGetSymbolAddress((void**)&b2hi, g_B2hi);
    cudaGetSymbolAddress((void**)&b2lo, g_B2lo);
    cudaGetSymbolAddress((void**)&qhi,  g_qhi);
    cudaGetSymbolAddress((void**)&qlo,  g_qlo);

    const dim3 gridG(512 / 64, ROWS / 64);  // (8, 48)
    const dim3 gridA(32, 8, 3);

    split_all<<<(NX4 + 2 * NW4) / 256, 256>>>(x, Wq, Wo);
    gemm_bf16<<<gridG, 128>>>(ahi, alo, bhi, blo, nullptr, nullptr, qhi, qlo,
                              ROWS, 512, 512);
    k1_scores<<<gridA, 128>>>();
    k2_mid  <<<gridA, 128>>>();
    k3_out  <<<gridA, 128>>>();
    gemm_bf16<<<gridG, 128>>>(ahi, alo, b2hi, b2lo, bo, out, nullptr, nullptr,
                              ROWS, 512, 512);
}